// round 1
// baseline (speedup 1.0000x reference)
#include <cuda_runtime.h>
#include <math.h>

#define NMAX 200000
#define DD   256
#define BMAX 64
#define CHUNK 256

// ---------------- scratch (no allocations allowed) ----------------
__device__ float g_k[2][NMAX];
__device__ float g_q[2][NMAX];
__device__ float g_v[2][NMAX];
__device__ float g_m[2][NMAX];      // per-dst running max of logits
__device__ float g_s[2][NMAX];      // per-dst sum of exp
__device__ float g_num[2][NMAX];    // per-dst sum of exp * val
__device__ float g_score[2][NMAX];  // per-node pooling score
__device__ float g_Mb[2][BMAX];     // per-batch max of score
__device__ float g_Sb[2][BMAX];     // per-batch sum of exp(score - Mb)
__device__ float g_wsum[2];         // sum of w_inst / w_net

__device__ __forceinline__ void atomicMaxF(float* addr, float val) {
    // float ordering == int ordering for >=0, reversed-unsigned for <0
    if (val >= 0.0f) atomicMax((int*)addr, __float_as_int(val));
    else             atomicMin((unsigned int*)addr, __float_as_uint(val));
}

// ---------------- init ----------------
__global__ void init_kernel() {
    int i = blockIdx.x * blockDim.x + threadIdx.x;
    int stride = gridDim.x * blockDim.x;
    for (int j = i; j < NMAX; j += stride) {
        g_m[0][j] = -INFINITY; g_m[1][j] = -INFINITY;
        g_s[0][j] = 0.0f;      g_s[1][j] = 0.0f;
        g_num[0][j] = 0.0f;    g_num[1][j] = 0.0f;
    }
    if (i < BMAX) {
        g_Mb[0][i] = -INFINITY; g_Mb[1][i] = -INFINITY;
        g_Sb[0][i] = 0.0f;      g_Sb[1][i] = 0.0f;
    }
}

// ---------------- sum of w vectors (256 floats each) ----------------
__global__ void wsum_kernel(const float* __restrict__ wa, const float* __restrict__ wb) {
    const float* w = blockIdx.x ? wb : wa;
    __shared__ float sh[8];
    float v = w[threadIdx.x];
    #pragma unroll
    for (int o = 16; o; o >>= 1) v += __shfl_xor_sync(0xffffffffu, v, o);
    if ((threadIdx.x & 31) == 0) sh[threadIdx.x >> 5] = v;
    __syncthreads();
    if (threadIdx.x == 0) {
        float t = 0.0f;
        #pragma unroll
        for (int j = 0; j < 8; j++) t += sh[j];
        g_wsum[blockIdx.x] = t;
    }
}

// ---------------- kqv: [N,256] @ [256,3] per-node scalars ----------------
__global__ void kqv_kernel(const float* __restrict__ x, const float* __restrict__ W,
                           const float* __restrict__ b, int N, int graph) {
    int gtid = blockIdx.x * blockDim.x + threadIdx.x;
    int warp = gtid >> 5, lane = gtid & 31;
    int nwarps = (gridDim.x * blockDim.x) >> 5;

    // per-lane weight slice is constant across nodes: hoist into registers
    float wk[8], wq[8], wv[8];
    #pragma unroll
    for (int i = 0; i < 2; i++) {
        #pragma unroll
        for (int c = 0; c < 4; c++) {
            int d = (lane + 32 * i) * 4 + c;
            wk[i * 4 + c] = W[d * 3 + 0];
            wq[i * 4 + c] = W[d * 3 + 1];
            wv[i * 4 + c] = W[d * 3 + 2];
        }
    }
    float b0 = b[0], b1 = b[1], b2 = b[2];

    for (int n = warp; n < N; n += nwarps) {
        const float4* x4 = (const float4*)(x + (size_t)n * DD);
        float pk = 0.f, pq = 0.f, pv = 0.f;
        #pragma unroll
        for (int i = 0; i < 2; i++) {
            float4 xv = __ldg(&x4[lane + 32 * i]);
            pk += xv.x * wk[i*4+0] + xv.y * wk[i*4+1] + xv.z * wk[i*4+2] + xv.w * wk[i*4+3];
            pq += xv.x * wq[i*4+0] + xv.y * wq[i*4+1] + xv.z * wq[i*4+2] + xv.w * wq[i*4+3];
            pv += xv.x * wv[i*4+0] + xv.y * wv[i*4+1] + xv.z * wv[i*4+2] + xv.w * wv[i*4+3];
        }
        #pragma unroll
        for (int o = 16; o; o >>= 1) {
            pk += __shfl_xor_sync(0xffffffffu, pk, o);
            pq += __shfl_xor_sync(0xffffffffu, pq, o);
            pv += __shfl_xor_sync(0xffffffffu, pv, o);
        }
        if (lane == 0) {
            g_k[graph][n] = pk + b0;
            g_q[graph][n] = pq + b1;
            g_v[graph][n] = pv + b2;
        }
    }
}

// ---------------- edge pass A: per-dst max logit ----------------
__global__ void edge_max_kernel(const int* __restrict__ ei, int E, int qg, int kg,
                                const float* __restrict__ a, const float* __restrict__ p) {
    float sc = a[0] * p[0];  // SQRT_HD == 1.0
    const float* __restrict__ q = g_q[qg];
    const float* __restrict__ k = g_k[kg];
    float* m = g_m[qg];
    for (int e = blockIdx.x * blockDim.x + threadIdx.x; e < E; e += gridDim.x * blockDim.x) {
        int s = ei[e], d = ei[E + e];
        atomicMaxF(&m[d], q[d] * k[s] * sc);
    }
}

// ---------------- edge pass B: sum exp + sum exp*val ----------------
__global__ void edge_sum_kernel(const int* __restrict__ ei, int E, int qg, int kg,
                                const float* __restrict__ a, const float* __restrict__ p,
                                const float* __restrict__ mscale) {
    float sc = a[0] * p[0];
    float ms = mscale[0];
    const float* __restrict__ q = g_q[qg];
    const float* __restrict__ k = g_k[kg];
    const float* __restrict__ v = g_v[kg];
    const float* __restrict__ m = g_m[qg];
    float* ss  = g_s[qg];
    float* num = g_num[qg];
    for (int e = blockIdx.x * blockDim.x + threadIdx.x; e < E; e += gridDim.x * blockDim.x) {
        int s = ei[e], d = ei[E + e];
        float ex = __expf(q[d] * k[s] * sc - m[d]);
        atomicAdd(&ss[d], ex);
        atomicAdd(&num[d], ex * v[s] * ms);
    }
}

// ---------------- per-node: agg -> gelu -> score -> batch max ----------------
__global__ void node_fin_kernel(int graph, int N,
                                const float* __restrict__ outw, const float* __restrict__ outb,
                                const float* __restrict__ bvec, const int* __restrict__ batch) {
    float ow = outw[0], ob = outb[0];
    float wsum = g_wsum[graph];
    float boff = (float)DD * bvec[0];
    for (int n = blockIdx.x * blockDim.x + threadIdx.x; n < N; n += gridDim.x * blockDim.x) {
        float agg = g_num[graph][n] / (g_s[graph][n] + 1e-16f);
        float attn = 0.5f * agg * (1.0f + erff(agg * 0.70710678118654752f)) * ow + ob;
        float sc = attn * wsum + boff;
        g_score[graph][n] = sc;
        atomicMaxF(&g_Mb[graph][batch[n]], sc);
    }
}

// ---------------- pooling: out[b,:] += exp(score-Mb)*x[n,:]; Sb += exp ----------------
// batch is sorted, so a block's chunk touches very few batch ids.
__global__ void pool_kernel(const float* __restrict__ x, const int* __restrict__ batch,
                            int graph, int N, float* __restrict__ out) {
    int t = threadIdx.x;                 // 0..255, one feature dim per thread
    int start = blockIdx.x * CHUNK;
    if (start >= N) return;
    int end = min(start + CHUNK, N);

    const float* __restrict__ score = g_score[graph];
    const float* __restrict__ Mb = g_Mb[graph];

    float acc = 0.0f, wl = 0.0f;
    int cur = batch[start];
    float Mcur = Mb[cur];
    for (int n = start; n < end; n++) {
        int b = batch[n];
        if (b != cur) {
            atomicAdd(&out[(size_t)cur * DD + t], acc);
            if (t == 0) atomicAdd(&g_Sb[graph][cur], wl);
            acc = 0.0f; wl = 0.0f; cur = b; Mcur = Mb[b];
        }
        float w = __expf(score[n] - Mcur);
        acc += w * x[(size_t)n * DD + t];
        wl += w;
    }
    atomicAdd(&out[(size_t)cur * DD + t], acc);
    if (t == 0) atomicAdd(&g_Sb[graph][cur], wl);
}

// ---------------- final divide by Sb ----------------
__global__ void final_div_kernel(float* __restrict__ out) {
    int row = blockIdx.x;               // 0..127: graph*64 + batch
    int graph = row >> 6, b = row & 63;
    out[(size_t)row * DD + threadIdx.x] /= (g_Sb[graph][b] + 1e-16f);
}

extern "C" void kernel_launch(void* const* d_in, const int* in_sizes, int n_in,
                              void* d_out, int out_size) {
    const float* x_i   = (const float*)d_in[0];
    const float* x_n   = (const float*)d_in[1];
    const int*   ei_ii = (const int*)d_in[2];
    const int*   ei_in = (const int*)d_in[3];
    const int*   ei_ni = (const int*)d_in[4];
    const int*   b_i   = (const int*)d_in[5];
    const int*   b_n   = (const int*)d_in[6];
    const float* Wi    = (const float*)d_in[7];
    const float* bi    = (const float*)d_in[8];
    const float* Wn    = (const float*)d_in[9];
    const float* bn    = (const float*)d_in[10];
    const float* a_ii  = (const float*)d_in[11];
    const float* m_ii  = (const float*)d_in[12];
    const float* p_ii  = (const float*)d_in[13];
    const float* a_in  = (const float*)d_in[14];
    const float* m_in  = (const float*)d_in[15];
    const float* p_in  = (const float*)d_in[16];
    const float* a_ni  = (const float*)d_in[17];
    const float* m_ni  = (const float*)d_in[18];
    const float* p_ni  = (const float*)d_in[19];
    const float* outw_i = (const float*)d_in[20];
    const float* outb_i = (const float*)d_in[21];
    const float* outw_n = (const float*)d_in[22];
    const float* outb_n = (const float*)d_in[23];
    const float* w_i    = (const float*)d_in[24];
    const float* bv_i   = (const float*)d_in[25];
    const float* w_n    = (const float*)d_in[26];
    const float* bv_n   = (const float*)d_in[27];

    int Ni  = in_sizes[0] / DD;
    int Nn  = in_sizes[1] / DD;
    int Eii = in_sizes[2] / 2;
    int Ein = in_sizes[3] / 2;
    int Eni = in_sizes[4] / 2;

    float* out = (float*)d_out;

    cudaMemsetAsync(d_out, 0, (size_t)out_size * sizeof(float), 0);
    init_kernel<<<512, 256>>>();
    wsum_kernel<<<2, 256>>>(w_i, w_n);

    kqv_kernel<<<2048, 256>>>(x_i, Wi, bi, Ni, 0);
    kqv_kernel<<<2048, 256>>>(x_n, Wn, bn, Nn, 1);

    const int EB = 256;
    edge_max_kernel<<<(Eii + EB - 1) / EB, EB>>>(ei_ii, Eii, 0, 0, a_ii, p_ii);
    edge_max_kernel<<<(Eni + EB - 1) / EB, EB>>>(ei_ni, Eni, 0, 1, a_ni, p_ni);
    edge_max_kernel<<<(Ein + EB - 1) / EB, EB>>>(ei_in, Ein, 1, 0, a_in, p_in);

    edge_sum_kernel<<<(Eii + EB - 1) / EB, EB>>>(ei_ii, Eii, 0, 0, a_ii, p_ii, m_ii);
    edge_sum_kernel<<<(Eni + EB - 1) / EB, EB>>>(ei_ni, Eni, 0, 1, a_ni, p_ni, m_ni);
    edge_sum_kernel<<<(Ein + EB - 1) / EB, EB>>>(ei_in, Ein, 1, 0, a_in, p_in, m_in);

    node_fin_kernel<<<(Ni + 255) / 256, 256>>>(0, Ni, outw_i, outb_i, bv_i, b_i);
    node_fin_kernel<<<(Nn + 255) / 256, 256>>>(1, Nn, outw_n, outb_n, bv_n, b_n);

    pool_kernel<<<(Ni + CHUNK - 1) / CHUNK, 256>>>(x_i, b_i, 0, Ni, out);
    pool_kernel<<<(Nn + CHUNK - 1) / CHUNK, 256>>>(x_n, b_n, 1, Nn, out + (size_t)BMAX * DD);

    final_div_kernel<<<2 * BMAX, 256>>>(out);
}

// round 2
// speedup vs baseline: 2.1582x; 2.1582x over previous
#include <cuda_runtime.h>
#include <math.h>

#define NMAX 200000
#define DD   256
#define BMAX 64
#define POOL_CHUNK 64

// ---------------- scratch (no allocations allowed) ----------------
__device__ float2 g_kv[2][NMAX];     // (k, v) packed per node
__device__ float  g_q[2][NMAX];
__device__ float  g_m[2][NMAX];      // per-dst max logit
__device__ float2 g_qm[2][NMAX];     // (q, m) packed per node
__device__ float  g_s[2][NMAX];      // per-dst sum exp
__device__ float  g_num[2][NMAX];    // per-dst sum exp*val
__device__ float  g_score[2][NMAX];  // pooling score
__device__ float  g_w[2][NMAX];      // exp(score - Mb)
__device__ float  g_Mb[2][BMAX];
__device__ float  g_Sb[2][BMAX];
__device__ float  g_wsum[2];

__device__ __forceinline__ void atomicMaxF(float* addr, float val) {
    if (val >= 0.0f) atomicMax((int*)addr, __float_as_int(val));
    else             atomicMin((unsigned int*)addr, __float_as_uint(val));
}

// ---------------- init ----------------
__global__ void init_kernel() {
    int i = blockIdx.x * blockDim.x + threadIdx.x;
    int stride = gridDim.x * blockDim.x;
    for (int j = i; j < NMAX; j += stride) {
        g_m[0][j] = -INFINITY; g_m[1][j] = -INFINITY;
        g_s[0][j] = 0.0f;      g_s[1][j] = 0.0f;
        g_num[0][j] = 0.0f;    g_num[1][j] = 0.0f;
    }
    if (i < BMAX) {
        g_Mb[0][i] = -INFINITY; g_Mb[1][i] = -INFINITY;
        g_Sb[0][i] = 0.0f;      g_Sb[1][i] = 0.0f;
    }
}

// ---------------- sum of w vectors ----------------
__global__ void wsum_kernel(const float* __restrict__ wa, const float* __restrict__ wb) {
    const float* w = blockIdx.x ? wb : wa;
    __shared__ float sh[8];
    float v = w[threadIdx.x];
    #pragma unroll
    for (int o = 16; o; o >>= 1) v += __shfl_xor_sync(0xffffffffu, v, o);
    if ((threadIdx.x & 31) == 0) sh[threadIdx.x >> 5] = v;
    __syncthreads();
    if (threadIdx.x == 0) {
        float t = 0.0f;
        #pragma unroll
        for (int j = 0; j < 8; j++) t += sh[j];
        g_wsum[blockIdx.x] = t;
    }
}

// ---------------- kqv: both graphs, 2 nodes per warp iteration ----------------
__global__ void kqv_kernel(const float* __restrict__ xi, const float* __restrict__ xn,
                           const float* __restrict__ Wi, const float* __restrict__ Wn,
                           const float* __restrict__ bI, const float* __restrict__ bN,
                           int Ni, int Nn) {
    int g = blockIdx.y;
    const float* __restrict__ x = g ? xn : xi;
    const float* __restrict__ W = g ? Wn : Wi;
    const float* __restrict__ bb = g ? bN : bI;
    int N = g ? Nn : Ni;

    int gtid = blockIdx.x * blockDim.x + threadIdx.x;
    int warp = gtid >> 5, lane = gtid & 31;
    int nwarps = (gridDim.x * blockDim.x) >> 5;

    float wk[8], wq[8], wv[8];
    #pragma unroll
    for (int i = 0; i < 2; i++) {
        #pragma unroll
        for (int c = 0; c < 4; c++) {
            int d = (lane + 32 * i) * 4 + c;
            wk[i * 4 + c] = W[d * 3 + 0];
            wq[i * 4 + c] = W[d * 3 + 1];
            wv[i * 4 + c] = W[d * 3 + 2];
        }
    }
    float b0 = bb[0], b1 = bb[1], b2 = bb[2];

    for (int n = warp * 2; n < N; n += nwarps * 2) {
        bool two = (n + 1 < N);
        const float4* xa = (const float4*)(x + (size_t)n * DD);
        const float4* xb = (const float4*)(x + (size_t)(two ? n + 1 : n) * DD);
        float4 a0 = __ldg(&xa[lane]);
        float4 a1 = __ldg(&xa[lane + 32]);
        float4 c0 = __ldg(&xb[lane]);
        float4 c1 = __ldg(&xb[lane + 32]);

        float ka, qa, va, kc, qc, vc;
        ka = a0.x*wk[0] + a0.y*wk[1] + a0.z*wk[2] + a0.w*wk[3]
           + a1.x*wk[4] + a1.y*wk[5] + a1.z*wk[6] + a1.w*wk[7];
        qa = a0.x*wq[0] + a0.y*wq[1] + a0.z*wq[2] + a0.w*wq[3]
           + a1.x*wq[4] + a1.y*wq[5] + a1.z*wq[6] + a1.w*wq[7];
        va = a0.x*wv[0] + a0.y*wv[1] + a0.z*wv[2] + a0.w*wv[3]
           + a1.x*wv[4] + a1.y*wv[5] + a1.z*wv[6] + a1.w*wv[7];
        kc = c0.x*wk[0] + c0.y*wk[1] + c0.z*wk[2] + c0.w*wk[3]
           + c1.x*wk[4] + c1.y*wk[5] + c1.z*wk[6] + c1.w*wk[7];
        qc = c0.x*wq[0] + c0.y*wq[1] + c0.z*wq[2] + c0.w*wq[3]
           + c1.x*wq[4] + c1.y*wq[5] + c1.z*wq[6] + c1.w*wq[7];
        vc = c0.x*wv[0] + c0.y*wv[1] + c0.z*wv[2] + c0.w*wv[3]
           + c1.x*wv[4] + c1.y*wv[5] + c1.z*wv[6] + c1.w*wv[7];

        #pragma unroll
        for (int o = 16; o; o >>= 1) {
            ka += __shfl_xor_sync(0xffffffffu, ka, o);
            qa += __shfl_xor_sync(0xffffffffu, qa, o);
            va += __shfl_xor_sync(0xffffffffu, va, o);
            kc += __shfl_xor_sync(0xffffffffu, kc, o);
            qc += __shfl_xor_sync(0xffffffffu, qc, o);
            vc += __shfl_xor_sync(0xffffffffu, vc, o);
        }
        if (lane == 0) {
            g_kv[g][n] = make_float2(ka + b0, va + b2);
            g_q[g][n]  = qa + b1;
            if (two) {
                g_kv[g][n + 1] = make_float2(kc + b0, vc + b2);
                g_q[g][n + 1]  = qc + b1;
            }
        }
    }
}

// ---------------- edge pass A: per-dst max logit (3 edge types fused) ----------------
__global__ void edge_max_kernel(const int* __restrict__ ii, const int* __restrict__ ni,
                                const int* __restrict__ in_,
                                int Eii, int Eni, int Ein,
                                const float* aii, const float* pii,
                                const float* ani, const float* pni,
                                const float* ain, const float* pin_) {
    int y = blockIdx.y;
    const int* __restrict__ ei; int E; const float2* __restrict__ kv;
    const float* __restrict__ q; float* m; float sc;
    if (y == 0)      { ei = ii;  E = Eii; kv = g_kv[0]; q = g_q[0]; m = g_m[0]; sc = aii[0]*pii[0]; }
    else if (y == 1) { ei = ni;  E = Eni; kv = g_kv[1]; q = g_q[0]; m = g_m[0]; sc = ani[0]*pni[0]; }
    else             { ei = in_; E = Ein; kv = g_kv[0]; q = g_q[1]; m = g_m[1]; sc = ain[0]*pin_[0]; }

    int stride = gridDim.x * blockDim.x * 4;
    for (int e = (blockIdx.x * blockDim.x + threadIdx.x) * 4; e < E; e += stride) {
        if (e + 4 <= E) {
            int s0 = __ldg(ei + e),     s1 = __ldg(ei + e + 1);
            int s2 = __ldg(ei + e + 2), s3 = __ldg(ei + e + 3);
            int d0 = __ldg(ei + E + e),     d1 = __ldg(ei + E + e + 1);
            int d2 = __ldg(ei + E + e + 2), d3 = __ldg(ei + E + e + 3);
            float y0 = kv[s0].x * sc, y1 = kv[s1].x * sc;
            float y2 = kv[s2].x * sc, y3 = kv[s3].x * sc;
            float q0 = q[d0], q1 = q[d1], q2 = q[d2], q3 = q[d3];
            atomicMaxF(&m[d0], q0 * y0);
            atomicMaxF(&m[d1], q1 * y1);
            atomicMaxF(&m[d2], q2 * y2);
            atomicMaxF(&m[d3], q3 * y3);
        } else {
            for (int t = e; t < E; t++) {
                int s = __ldg(ei + t), d = __ldg(ei + E + t);
                atomicMaxF(&m[d], q[d] * (kv[s].x * sc));
            }
        }
    }
}

// ---------------- pack (q, m) for pass B ----------------
__global__ void pack_qm_kernel(int Ni, int Nn) {
    int g = blockIdx.y;
    int N = g ? Nn : Ni;
    int stride = gridDim.x * blockDim.x;
    for (int n = blockIdx.x * blockDim.x + threadIdx.x; n < N; n += stride)
        g_qm[g][n] = make_float2(g_q[g][n], g_m[g][n]);
}

// ---------------- edge pass B: sum exp + sum exp*val (fused) ----------------
__global__ void edge_sum_kernel(const int* __restrict__ ii, const int* __restrict__ ni,
                                const int* __restrict__ in_,
                                int Eii, int Eni, int Ein,
                                const float* aii, const float* pii, const float* mii,
                                const float* ani, const float* pni, const float* mni,
                                const float* ain, const float* pin_, const float* min_) {
    int y = blockIdx.y;
    const int* __restrict__ ei; int E; const float2* __restrict__ kv;
    const float2* __restrict__ qm; float *S, *NUM; float sc, ms;
    if (y == 0)      { ei = ii;  E = Eii; kv = g_kv[0]; qm = g_qm[0]; S = g_s[0]; NUM = g_num[0]; sc = aii[0]*pii[0]; ms = mii[0]; }
    else if (y == 1) { ei = ni;  E = Eni; kv = g_kv[1]; qm = g_qm[0]; S = g_s[0]; NUM = g_num[0]; sc = ani[0]*pni[0]; ms = mni[0]; }
    else             { ei = in_; E = Ein; kv = g_kv[0]; qm = g_qm[1]; S = g_s[1]; NUM = g_num[1]; sc = ain[0]*pin_[0]; ms = min_[0]; }

    int stride = gridDim.x * blockDim.x * 4;
    for (int e = (blockIdx.x * blockDim.x + threadIdx.x) * 4; e < E; e += stride) {
        if (e + 4 <= E) {
            int s0 = __ldg(ei + e),     s1 = __ldg(ei + e + 1);
            int s2 = __ldg(ei + e + 2), s3 = __ldg(ei + e + 3);
            int d0 = __ldg(ei + E + e),     d1 = __ldg(ei + E + e + 1);
            int d2 = __ldg(ei + E + e + 2), d3 = __ldg(ei + E + e + 3);
            float2 kv0 = kv[s0], kv1 = kv[s1], kv2 = kv[s2], kv3 = kv[s3];
            float2 qm0 = qm[d0], qm1 = qm[d1], qm2 = qm[d2], qm3 = qm[d3];
            float e0 = __expf(qm0.x * kv0.x * sc - qm0.y);
            float e1 = __expf(qm1.x * kv1.x * sc - qm1.y);
            float e2 = __expf(qm2.x * kv2.x * sc - qm2.y);
            float e3 = __expf(qm3.x * kv3.x * sc - qm3.y);
            atomicAdd(&S[d0], e0);  atomicAdd(&NUM[d0], e0 * kv0.y * ms);
            atomicAdd(&S[d1], e1);  atomicAdd(&NUM[d1], e1 * kv1.y * ms);
            atomicAdd(&S[d2], e2);  atomicAdd(&NUM[d2], e2 * kv2.y * ms);
            atomicAdd(&S[d3], e3);  atomicAdd(&NUM[d3], e3 * kv3.y * ms);
        } else {
            for (int t = e; t < E; t++) {
                int s = __ldg(ei + t), d = __ldg(ei + E + t);
                float2 kvv = kv[s]; float2 qmv = qm[d];
                float ex = __expf(qmv.x * kvv.x * sc - qmv.y);
                atomicAdd(&S[d], ex);
                atomicAdd(&NUM[d], ex * kvv.y * ms);
            }
        }
    }
}

// ---------------- per-node: agg -> gelu -> score -> batch max (warp-aggregated) ----------------
__global__ void node_fin_kernel(const float* owi, const float* obi,
                                const float* own, const float* obn,
                                const float* bvi, const float* bvn,
                                const int* __restrict__ bti, const int* __restrict__ btn,
                                int Ni, int Nn) {
    int g = blockIdx.y;
    int N = g ? Nn : Ni;
    const int* __restrict__ batch = g ? btn : bti;
    float ow = g ? own[0] : owi[0];
    float ob = g ? obn[0] : obi[0];
    float wsum = g_wsum[g];
    float boff = (float)DD * (g ? bvn[0] : bvi[0]);

    int n = blockIdx.x * blockDim.x + threadIdx.x;
    int nc = min(n, N - 1);
    int b = batch[nc];
    float sc = -INFINITY;
    if (n < N) {
        float agg = g_num[g][n] / (g_s[g][n] + 1e-16f);
        float attn = 0.5f * agg * (1.0f + erff(agg * 0.70710678118654752f)) * ow + ob;
        sc = attn * wsum + boff;
        g_score[g][n] = sc;
    }
    int b0 = __shfl_sync(0xffffffffu, b, 0);
    bool uni = __all_sync(0xffffffffu, b == b0);
    if (uni) {
        float v = sc;
        #pragma unroll
        for (int o = 16; o; o >>= 1) v = fmaxf(v, __shfl_xor_sync(0xffffffffu, v, o));
        if ((threadIdx.x & 31) == 0) atomicMaxF(&g_Mb[g][b0], v);
    } else if (n < N) {
        atomicMaxF(&g_Mb[g][b], sc);
    }
}

// ---------------- per-node: w = exp(score - Mb), Sb (warp-aggregated) ----------------
__global__ void node_w_kernel(const int* __restrict__ bti, const int* __restrict__ btn,
                              int Ni, int Nn) {
    int g = blockIdx.y;
    int N = g ? Nn : Ni;
    const int* __restrict__ batch = g ? btn : bti;

    int n = blockIdx.x * blockDim.x + threadIdx.x;
    int nc = min(n, N - 1);
    int b = batch[nc];
    float w = 0.0f;
    if (n < N) {
        w = __expf(g_score[g][n] - g_Mb[g][b]);
        g_w[g][n] = w;
    }
    int b0 = __shfl_sync(0xffffffffu, b, 0);
    bool uni = __all_sync(0xffffffffu, b == b0);
    if (uni) {
        float v = w;
        #pragma unroll
        for (int o = 16; o; o >>= 1) v += __shfl_xor_sync(0xffffffffu, v, o);
        if ((threadIdx.x & 31) == 0) atomicAdd(&g_Sb[g][b0], v);
    } else if (n < N) {
        atomicAdd(&g_Sb[g][b], w);
    }
}

// ---------------- pooling: run-segmented weighted sum ----------------
__global__ void pool_kernel(const float* __restrict__ xi, const float* __restrict__ xn,
                            const int* __restrict__ bti, const int* __restrict__ btn,
                            int Ni, int Nn, float* __restrict__ out) {
    int g = blockIdx.y;
    const float* __restrict__ x = g ? xn : xi;
    const int* __restrict__ batch = g ? btn : bti;
    int N = g ? Nn : Ni;
    const float* __restrict__ w = g_w[g];
    float* outg = out + (size_t)g * BMAX * DD;

    int start = blockIdx.x * POOL_CHUNK;
    if (start >= N) return;
    int len = min(POOL_CHUNK, N - start);

    __shared__ float sw[POOL_CHUNK];
    __shared__ int sb[POOL_CHUNK];
    int t = threadIdx.x;
    if (t < len) { sw[t] = w[start + t]; sb[t] = batch[start + t]; }
    __syncthreads();

    const float* xrow = x + (size_t)start * DD + t;
    int i = 0;
    while (i < len) {
        int b = sb[i];
        int j = i + 1;
        while (j < len && sb[j] == b) ++j;
        float acc = 0.0f;
        int r = i;
        for (; r + 4 <= j; r += 4) {
            float x0 = xrow[(size_t)r * DD];
            float x1 = xrow[(size_t)(r + 1) * DD];
            float x2 = xrow[(size_t)(r + 2) * DD];
            float x3 = xrow[(size_t)(r + 3) * DD];
            acc += sw[r] * x0 + sw[r + 1] * x1 + sw[r + 2] * x2 + sw[r + 3] * x3;
        }
        for (; r < j; ++r) acc += sw[r] * xrow[(size_t)r * DD];
        atomicAdd(&outg[(size_t)b * DD + t], acc);
        i = j;
    }
}

// ---------------- final divide by Sb ----------------
__global__ void final_div_kernel(float* __restrict__ out) {
    int row = blockIdx.x;
    int graph = row >> 6, b = row & 63;
    out[(size_t)row * DD + threadIdx.x] /= (g_Sb[graph][b] + 1e-16f);
}

extern "C" void kernel_launch(void* const* d_in, const int* in_sizes, int n_in,
                              void* d_out, int out_size) {
    const float* x_i   = (const float*)d_in[0];
    const float* x_n   = (const float*)d_in[1];
    const int*   ei_ii = (const int*)d_in[2];
    const int*   ei_in = (const int*)d_in[3];
    const int*   ei_ni = (const int*)d_in[4];
    const int*   b_i   = (const int*)d_in[5];
    const int*   b_n   = (const int*)d_in[6];
    const float* Wi    = (const float*)d_in[7];
    const float* bi    = (const float*)d_in[8];
    const float* Wn    = (const float*)d_in[9];
    const float* bn    = (const float*)d_in[10];
    const float* a_ii  = (const float*)d_in[11];
    const float* m_ii  = (const float*)d_in[12];
    const float* p_ii  = (const float*)d_in[13];
    const float* a_in  = (const float*)d_in[14];
    const float* m_in  = (const float*)d_in[15];
    const float* p_in  = (const float*)d_in[16];
    const float* a_ni  = (const float*)d_in[17];
    const float* m_ni  = (const float*)d_in[18];
    const float* p_ni  = (const float*)d_in[19];
    const float* outw_i = (const float*)d_in[20];
    const float* outb_i = (const float*)d_in[21];
    const float* outw_n = (const float*)d_in[22];
    const float* outb_n = (const float*)d_in[23];
    const float* w_i    = (const float*)d_in[24];
    const float* bv_i   = (const float*)d_in[25];
    const float* w_n    = (const float*)d_in[26];
    const float* bv_n   = (const float*)d_in[27];

    int Ni  = in_sizes[0] / DD;
    int Nn  = in_sizes[1] / DD;
    int Eii = in_sizes[2] / 2;
    int Ein = in_sizes[3] / 2;
    int Eni = in_sizes[4] / 2;
    int Nmax = Ni > Nn ? Ni : Nn;

    float* out = (float*)d_out;

    cudaMemsetAsync(d_out, 0, (size_t)out_size * sizeof(float), 0);
    init_kernel<<<512, 256>>>();
    wsum_kernel<<<2, 256>>>(w_i, w_n);

    kqv_kernel<<<dim3(1024, 2), 256>>>(x_i, x_n, Wi, Wn, bi, bn, Ni, Nn);

    edge_max_kernel<<<dim3(1536, 3), 256>>>(ei_ii, ei_ni, ei_in, Eii, Eni, Ein,
                                            a_ii, p_ii, a_ni, p_ni, a_in, p_in);
    pack_qm_kernel<<<dim3(256, 2), 256>>>(Ni, Nn);
    edge_sum_kernel<<<dim3(1536, 3), 256>>>(ei_ii, ei_ni, ei_in, Eii, Eni, Ein,
                                            a_ii, p_ii, m_ii, a_ni, p_ni, m_ni,
                                            a_in, p_in, m_in);

    int nblk = (Nmax + 255) / 256;
    node_fin_kernel<<<dim3(nblk, 2), 256>>>(outw_i, outb_i, outw_n, outb_n,
                                            bv_i, bv_n, b_i, b_n, Ni, Nn);
    node_w_kernel<<<dim3(nblk, 2), 256>>>(b_i, b_n, Ni, Nn);

    pool_kernel<<<dim3((Nmax + POOL_CHUNK - 1) / POOL_CHUNK, 2), 256>>>(
        x_i, x_n, b_i, b_n, Ni, Nn, out);

    final_div_kernel<<<2 * BMAX, 256>>>(out);
}

// round 3
// speedup vs baseline: 2.2987x; 1.0651x over previous
#include <cuda_runtime.h>
#include <math.h>

#define NMAX 200000
#define DD   256
#define BMAX 64
#define POOL_CHUNK 64

// ---------------- scratch (no allocations allowed) ----------------
__device__ float2 g_kv[2][NMAX];     // (k, v) packed per node
__device__ float  g_q[2][NMAX];
__device__ float2 g_qm[2][NMAX];     // (q, m) packed per dst node
__device__ float2 g_sn[2][NMAX];     // (sum e, sum e*v*ms) per dst node
__device__ float2 g_knn_ii[NMAX];    // per-inst-dst (kmax, -kmin) over ii edges
__device__ float2 g_knn_ni[NMAX];    // per-inst-dst (kmax, -kmin) over ni edges
__device__ float2 g_knn_in[NMAX];    // per-net-dst  (kmax, -kmin) over in edges
__device__ float  g_score[2][NMAX];
__device__ float  g_w[2][NMAX];
__device__ float  g_Mb[2][BMAX];
__device__ float  g_Sb[2][BMAX];
__device__ float  g_wsum[2];

__device__ __forceinline__ void atomicMaxF(float* addr, float val) {
    if (val >= 0.0f) atomicMax((int*)addr, __float_as_int(val));
    else             atomicMin((unsigned int*)addr, __float_as_uint(val));
}

__device__ __forceinline__ void redAddF2(float2* addr, float a, float b) {
    unsigned long long p = (unsigned long long)__cvta_generic_to_global((void*)addr);
    asm volatile("red.global.add.v2.f32 [%0], {%1, %2};" :: "l"(p), "f"(a), "f"(b) : "memory");
}

// ---------------- init ----------------
__global__ void init_kernel() {
    int i = blockIdx.x * blockDim.x + threadIdx.x;
    int stride = gridDim.x * blockDim.x;
    float2 ninf2 = make_float2(-INFINITY, -INFINITY);
    float2 zero2 = make_float2(0.0f, 0.0f);
    for (int j = i; j < NMAX; j += stride) {
        g_knn_ii[j] = ninf2; g_knn_ni[j] = ninf2; g_knn_in[j] = ninf2;
        g_sn[0][j] = zero2;  g_sn[1][j] = zero2;
    }
    if (i < BMAX) {
        g_Mb[0][i] = -INFINITY; g_Mb[1][i] = -INFINITY;
        g_Sb[0][i] = 0.0f;      g_Sb[1][i] = 0.0f;
    }
}

// ---------------- sum of w vectors ----------------
__global__ void wsum_kernel(const float* __restrict__ wa, const float* __restrict__ wb) {
    const float* w = blockIdx.x ? wb : wa;
    __shared__ float sh[8];
    float v = w[threadIdx.x];
    #pragma unroll
    for (int o = 16; o; o >>= 1) v += __shfl_xor_sync(0xffffffffu, v, o);
    if ((threadIdx.x & 31) == 0) sh[threadIdx.x >> 5] = v;
    __syncthreads();
    if (threadIdx.x == 0) {
        float t = 0.0f;
        #pragma unroll
        for (int j = 0; j < 8; j++) t += sh[j];
        g_wsum[blockIdx.x] = t;
    }
}

// ---------------- kqv: both graphs, 2 nodes per warp iteration ----------------
__global__ void kqv_kernel(const float* __restrict__ xi, const float* __restrict__ xn,
                           const float* __restrict__ Wi, const float* __restrict__ Wn,
                           const float* __restrict__ bI, const float* __restrict__ bN,
                           int Ni, int Nn) {
    int g = blockIdx.y;
    const float* __restrict__ x = g ? xn : xi;
    const float* __restrict__ W = g ? Wn : Wi;
    const float* __restrict__ bb = g ? bN : bI;
    int N = g ? Nn : Ni;

    int gtid = blockIdx.x * blockDim.x + threadIdx.x;
    int warp = gtid >> 5, lane = gtid & 31;
    int nwarps = (gridDim.x * blockDim.x) >> 5;

    float wk[8], wq[8], wv[8];
    #pragma unroll
    for (int i = 0; i < 2; i++) {
        #pragma unroll
        for (int c = 0; c < 4; c++) {
            int d = (lane + 32 * i) * 4 + c;
            wk[i * 4 + c] = W[d * 3 + 0];
            wq[i * 4 + c] = W[d * 3 + 1];
            wv[i * 4 + c] = W[d * 3 + 2];
        }
    }
    float b0 = bb[0], b1 = bb[1], b2 = bb[2];

    for (int n = warp * 2; n < N; n += nwarps * 2) {
        bool two = (n + 1 < N);
        const float4* xa = (const float4*)(x + (size_t)n * DD);
        const float4* xb = (const float4*)(x + (size_t)(two ? n + 1 : n) * DD);
        float4 a0 = __ldg(&xa[lane]);
        float4 a1 = __ldg(&xa[lane + 32]);
        float4 c0 = __ldg(&xb[lane]);
        float4 c1 = __ldg(&xb[lane + 32]);

        float ka, qa, va, kc, qc, vc;
        ka = a0.x*wk[0] + a0.y*wk[1] + a0.z*wk[2] + a0.w*wk[3]
           + a1.x*wk[4] + a1.y*wk[5] + a1.z*wk[6] + a1.w*wk[7];
        qa = a0.x*wq[0] + a0.y*wq[1] + a0.z*wq[2] + a0.w*wq[3]
           + a1.x*wq[4] + a1.y*wq[5] + a1.z*wq[6] + a1.w*wq[7];
        va = a0.x*wv[0] + a0.y*wv[1] + a0.z*wv[2] + a0.w*wv[3]
           + a1.x*wv[4] + a1.y*wv[5] + a1.z*wv[6] + a1.w*wv[7];
        kc = c0.x*wk[0] + c0.y*wk[1] + c0.z*wk[2] + c0.w*wk[3]
           + c1.x*wk[4] + c1.y*wk[5] + c1.z*wk[6] + c1.w*wk[7];
        qc = c0.x*wq[0] + c0.y*wq[1] + c0.z*wq[2] + c0.w*wq[3]
           + c1.x*wq[4] + c1.y*wq[5] + c1.z*wq[6] + c1.w*wq[7];
        vc = c0.x*wv[0] + c0.y*wv[1] + c0.z*wv[2] + c0.w*wv[3]
           + c1.x*wv[4] + c1.y*wv[5] + c1.z*wv[6] + c1.w*wv[7];

        #pragma unroll
        for (int o = 16; o; o >>= 1) {
            ka += __shfl_xor_sync(0xffffffffu, ka, o);
            qa += __shfl_xor_sync(0xffffffffu, qa, o);
            va += __shfl_xor_sync(0xffffffffu, va, o);
            kc += __shfl_xor_sync(0xffffffffu, kc, o);
            qc += __shfl_xor_sync(0xffffffffu, qc, o);
            vc += __shfl_xor_sync(0xffffffffu, vc, o);
        }
        if (lane == 0) {
            g_kv[g][n] = make_float2(ka + b0, va + b2);
            g_q[g][n]  = qa + b1;
            if (two) {
                g_kv[g][n + 1] = make_float2(kc + b0, vc + b2);
                g_q[g][n + 1]  = qc + b1;
            }
        }
    }
}

// ---------------- edge pass A: per-(dst, edge-type) kmax / -kmin ----------------
// No q gather needed: max logit is reconstructed from (kmax, kmin) per dst.
__global__ void edge_max_kernel(const int* __restrict__ ii, const int* __restrict__ ni,
                                const int* __restrict__ in_,
                                int Eii, int Eni, int Ein) {
    int y = blockIdx.y;
    const int* __restrict__ ei; int E; const float2* __restrict__ kv; float2* knn;
    if (y == 0)      { ei = ii;  E = Eii; kv = g_kv[0]; knn = g_knn_ii; }
    else if (y == 1) { ei = ni;  E = Eni; kv = g_kv[1]; knn = g_knn_ni; }
    else             { ei = in_; E = Ein; kv = g_kv[0]; knn = g_knn_in; }

    int stride = gridDim.x * blockDim.x * 4;
    for (int e = (blockIdx.x * blockDim.x + threadIdx.x) * 4; e < E; e += stride) {
        if (e + 4 <= E) {
            int s0 = __ldg(ei + e),     s1 = __ldg(ei + e + 1);
            int s2 = __ldg(ei + e + 2), s3 = __ldg(ei + e + 3);
            int d0 = __ldg(ei + E + e),     d1 = __ldg(ei + E + e + 1);
            int d2 = __ldg(ei + E + e + 2), d3 = __ldg(ei + E + e + 3);
            float k0 = kv[s0].x, k1 = kv[s1].x, k2 = kv[s2].x, k3 = kv[s3].x;
            atomicMaxF(&knn[d0].x, k0);  atomicMaxF(&knn[d0].y, -k0);
            atomicMaxF(&knn[d1].x, k1);  atomicMaxF(&knn[d1].y, -k1);
            atomicMaxF(&knn[d2].x, k2);  atomicMaxF(&knn[d2].y, -k2);
            atomicMaxF(&knn[d3].x, k3);  atomicMaxF(&knn[d3].y, -k3);
        } else {
            for (int t = e; t < E; t++) {
                int s = __ldg(ei + t), d = __ldg(ei + E + t);
                float k = kv[s].x;
                atomicMaxF(&knn[d].x, k);
                atomicMaxF(&knn[d].y, -k);
            }
        }
    }
}

// ---------------- node mid pass: m[d] from (q, kmax, kmin); pack (q, m) ----------------
__device__ __forceinline__ float knn_term(float q, float sc, float2 knn) {
    if (knn.x == -INFINITY) return -INFINITY;   // empty neighborhood for this type
    float qsc = q * sc;
    return fmaxf(qsc * knn.x, qsc * (-knn.y));  // max of linear fn at endpoints
}

__global__ void node_mid_kernel(int Ni, int Nn,
                                const float* aii, const float* pii,
                                const float* ani, const float* pni,
                                const float* ain, const float* pin_) {
    int g = blockIdx.y;
    int N = g ? Nn : Ni;
    int n = blockIdx.x * blockDim.x + threadIdx.x;
    if (n >= N) return;
    float q = g_q[g][n];
    float m;
    if (g == 0) {
        float sc_ii = aii[0] * pii[0];
        float sc_ni = ani[0] * pni[0];
        m = fmaxf(knn_term(q, sc_ii, g_knn_ii[n]), knn_term(q, sc_ni, g_knn_ni[n]));
    } else {
        float sc_in = ain[0] * pin_[0];
        m = knn_term(q, sc_in, g_knn_in[n]);
    }
    g_qm[g][n] = make_float2(q, m);
}

// ---------------- edge pass B: (sum e, sum e*v*ms) via one v2 reduction ----------------
__global__ void edge_sum_kernel(const int* __restrict__ ii, const int* __restrict__ ni,
                                const int* __restrict__ in_,
                                int Eii, int Eni, int Ein,
                                const float* aii, const float* pii, const float* mii,
                                const float* ani, const float* pni, const float* mni,
                                const float* ain, const float* pin_, const float* min_) {
    int y = blockIdx.y;
    const int* __restrict__ ei; int E; const float2* __restrict__ kv;
    const float2* __restrict__ qm; float2* SN; float sc, ms;
    if (y == 0)      { ei = ii;  E = Eii; kv = g_kv[0]; qm = g_qm[0]; SN = g_sn[0]; sc = aii[0]*pii[0]; ms = mii[0]; }
    else if (y == 1) { ei = ni;  E = Eni; kv = g_kv[1]; qm = g_qm[0]; SN = g_sn[0]; sc = ani[0]*pni[0]; ms = mni[0]; }
    else             { ei = in_; E = Ein; kv = g_kv[0]; qm = g_qm[1]; SN = g_sn[1]; sc = ain[0]*pin_[0]; ms = min_[0]; }

    int stride = gridDim.x * blockDim.x * 4;
    for (int e = (blockIdx.x * blockDim.x + threadIdx.x) * 4; e < E; e += stride) {
        if (e + 4 <= E) {
            int s0 = __ldg(ei + e),     s1 = __ldg(ei + e + 1);
            int s2 = __ldg(ei + e + 2), s3 = __ldg(ei + e + 3);
            int d0 = __ldg(ei + E + e),     d1 = __ldg(ei + E + e + 1);
            int d2 = __ldg(ei + E + e + 2), d3 = __ldg(ei + E + e + 3);
            float2 kv0 = kv[s0], kv1 = kv[s1], kv2 = kv[s2], kv3 = kv[s3];
            float2 qm0 = qm[d0], qm1 = qm[d1], qm2 = qm[d2], qm3 = qm[d3];
            float e0 = __expf(qm0.x * sc * kv0.x - qm0.y);
            float e1 = __expf(qm1.x * sc * kv1.x - qm1.y);
            float e2 = __expf(qm2.x * sc * kv2.x - qm2.y);
            float e3 = __expf(qm3.x * sc * kv3.x - qm3.y);
            redAddF2(&SN[d0], e0, e0 * kv0.y * ms);
            redAddF2(&SN[d1], e1, e1 * kv1.y * ms);
            redAddF2(&SN[d2], e2, e2 * kv2.y * ms);
            redAddF2(&SN[d3], e3, e3 * kv3.y * ms);
        } else {
            for (int t = e; t < E; t++) {
                int s = __ldg(ei + t), d = __ldg(ei + E + t);
                float2 kvv = kv[s]; float2 qmv = qm[d];
                float ex = __expf(qmv.x * sc * kvv.x - qmv.y);
                redAddF2(&SN[d], ex, ex * kvv.y * ms);
            }
        }
    }
}

// ---------------- per-node: agg -> gelu -> score -> batch max (warp-aggregated) ----------------
__global__ void node_fin_kernel(const float* owi, const float* obi,
                                const float* own, const float* obn,
                                const float* bvi, const float* bvn,
                                const int* __restrict__ bti, const int* __restrict__ btn,
                                int Ni, int Nn) {
    int g = blockIdx.y;
    int N = g ? Nn : Ni;
    const int* __restrict__ batch = g ? btn : bti;
    float ow = g ? own[0] : owi[0];
    float ob = g ? obn[0] : obi[0];
    float wsum = g_wsum[g];
    float boff = (float)DD * (g ? bvn[0] : bvi[0]);

    int n = blockIdx.x * blockDim.x + threadIdx.x;
    int nc = min(n, N - 1);
    int b = batch[nc];
    float sc = -INFINITY;
    if (n < N) {
        float2 sn = g_sn[g][n];
        float agg = sn.y / (sn.x + 1e-16f);
        float attn = 0.5f * agg * (1.0f + erff(agg * 0.70710678118654752f)) * ow + ob;
        sc = attn * wsum + boff;
        g_score[g][n] = sc;
    }
    int b0 = __shfl_sync(0xffffffffu, b, 0);
    bool uni = __all_sync(0xffffffffu, b == b0);
    if (uni) {
        float v = sc;
        #pragma unroll
        for (int o = 16; o; o >>= 1) v = fmaxf(v, __shfl_xor_sync(0xffffffffu, v, o));
        if ((threadIdx.x & 31) == 0) atomicMaxF(&g_Mb[g][b0], v);
    } else if (n < N) {
        atomicMaxF(&g_Mb[g][b], sc);
    }
}

// ---------------- per-node: w = exp(score - Mb), Sb (warp-aggregated) ----------------
__global__ void node_w_kernel(const int* __restrict__ bti, const int* __restrict__ btn,
                              int Ni, int Nn) {
    int g = blockIdx.y;
    int N = g ? Nn : Ni;
    const int* __restrict__ batch = g ? btn : bti;

    int n = blockIdx.x * blockDim.x + threadIdx.x;
    int nc = min(n, N - 1);
    int b = batch[nc];
    float w = 0.0f;
    if (n < N) {
        w = __expf(g_score[g][n] - g_Mb[g][b]);
        g_w[g][n] = w;
    }
    int b0 = __shfl_sync(0xffffffffu, b, 0);
    bool uni = __all_sync(0xffffffffu, b == b0);
    if (uni) {
        float v = w;
        #pragma unroll
        for (int o = 16; o; o >>= 1) v += __shfl_xor_sync(0xffffffffu, v, o);
        if ((threadIdx.x & 31) == 0) atomicAdd(&g_Sb[g][b0], v);
    } else if (n < N) {
        atomicAdd(&g_Sb[g][b], w);
    }
}

// ---------------- pooling: run-segmented weighted sum ----------------
__global__ void pool_kernel(const float* __restrict__ xi, const float* __restrict__ xn,
                            const int* __restrict__ bti, const int* __restrict__ btn,
                            int Ni, int Nn, float* __restrict__ out) {
    int g = blockIdx.y;
    const float* __restrict__ x = g ? xn : xi;
    const int* __restrict__ batch = g ? btn : bti;
    int N = g ? Nn : Ni;
    const float* __restrict__ w = g_w[g];
    float* outg = out + (size_t)g * BMAX * DD;

    int start = blockIdx.x * POOL_CHUNK;
    if (start >= N) return;
    int len = min(POOL_CHUNK, N - start);

    __shared__ float sw[POOL_CHUNK];
    __shared__ int sb[POOL_CHUNK];
    int t = threadIdx.x;
    if (t < len) { sw[t] = w[start + t]; sb[t] = batch[start + t]; }
    __syncthreads();

    const float* xrow = x + (size_t)start * DD + t;
    int i = 0;
    while (i < len) {
        int b = sb[i];
        int j = i + 1;
        while (j < len && sb[j] == b) ++j;
        float acc = 0.0f;
        int r = i;
        for (; r + 4 <= j; r += 4) {
            float x0 = xrow[(size_t)r * DD];
            float x1 = xrow[(size_t)(r + 1) * DD];
            float x2 = xrow[(size_t)(r + 2) * DD];
            float x3 = xrow[(size_t)(r + 3) * DD];
            acc += sw[r] * x0 + sw[r + 1] * x1 + sw[r + 2] * x2 + sw[r + 3] * x3;
        }
        for (; r < j; ++r) acc += sw[r] * xrow[(size_t)r * DD];
        atomicAdd(&outg[(size_t)b * DD + t], acc);
        i = j;
    }
}

// ---------------- final divide by Sb ----------------
__global__ void final_div_kernel(float* __restrict__ out) {
    int row = blockIdx.x;
    int graph = row >> 6, b = row & 63;
    out[(size_t)row * DD + threadIdx.x] /= (g_Sb[graph][b] + 1e-16f);
}

extern "C" void kernel_launch(void* const* d_in, const int* in_sizes, int n_in,
                              void* d_out, int out_size) {
    const float* x_i   = (const float*)d_in[0];
    const float* x_n   = (const float*)d_in[1];
    const int*   ei_ii = (const int*)d_in[2];
    const int*   ei_in = (const int*)d_in[3];
    const int*   ei_ni = (const int*)d_in[4];
    const int*   b_i   = (const int*)d_in[5];
    const int*   b_n   = (const int*)d_in[6];
    const float* Wi    = (const float*)d_in[7];
    const float* bi    = (const float*)d_in[8];
    const float* Wn    = (const float*)d_in[9];
    const float* bn    = (const float*)d_in[10];
    const float* a_ii  = (const float*)d_in[11];
    const float* m_ii  = (const float*)d_in[12];
    const float* p_ii  = (const float*)d_in[13];
    const float* a_in  = (const float*)d_in[14];
    const float* m_in  = (const float*)d_in[15];
    const float* p_in  = (const float*)d_in[16];
    const float* a_ni  = (const float*)d_in[17];
    const float* m_ni  = (const float*)d_in[18];
    const float* p_ni  = (const float*)d_in[19];
    const float* outw_i = (const float*)d_in[20];
    const float* outb_i = (const float*)d_in[21];
    const float* outw_n = (const float*)d_in[22];
    const float* outb_n = (const float*)d_in[23];
    const float* w_i    = (const float*)d_in[24];
    const float* bv_i   = (const float*)d_in[25];
    const float* w_n    = (const float*)d_in[26];
    const float* bv_n   = (const float*)d_in[27];

    int Ni  = in_sizes[0] / DD;
    int Nn  = in_sizes[1] / DD;
    int Eii = in_sizes[2] / 2;
    int Ein = in_sizes[3] / 2;
    int Eni = in_sizes[4] / 2;
    int Nmax = Ni > Nn ? Ni : Nn;

    float* out = (float*)d_out;

    cudaMemsetAsync(d_out, 0, (size_t)out_size * sizeof(float), 0);
    init_kernel<<<512, 256>>>();
    wsum_kernel<<<2, 256>>>(w_i, w_n);

    kqv_kernel<<<dim3(1024, 2), 256>>>(x_i, x_n, Wi, Wn, bi, bn, Ni, Nn);

    edge_max_kernel<<<dim3(1536, 3), 256>>>(ei_ii, ei_ni, ei_in, Eii, Eni, Ein);

    int nblk = (Nmax + 255) / 256;
    node_mid_kernel<<<dim3(nblk, 2), 256>>>(Ni, Nn, a_ii, p_ii, a_ni, p_ni, a_in, p_in);

    edge_sum_kernel<<<dim3(1536, 3), 256>>>(ei_ii, ei_ni, ei_in, Eii, Eni, Ein,
                                            a_ii, p_ii, m_ii, a_ni, p_ni, m_ni,
                                            a_in, p_in, m_in);

    node_fin_kernel<<<dim3(nblk, 2), 256>>>(outw_i, outb_i, outw_n, outb_n,
                                            bv_i, bv_n, b_i, b_n, Ni, Nn);
    node_w_kernel<<<dim3(nblk, 2), 256>>>(b_i, b_n, Ni, Nn);

    pool_kernel<<<dim3((Nmax + POOL_CHUNK - 1) / POOL_CHUNK, 2), 256>>>(
        x_i, x_n, b_i, b_n, Ni, Nn, out);

    final_div_kernel<<<2 * BMAX, 256>>>(out);
}

// round 4
// speedup vs baseline: 3.1900x; 1.3878x over previous
#include <cuda_runtime.h>
#include <math.h>

#define NMAX 200000
#define DD   256
#define BMAX 64
#define POOL_CHUNK 64
#define MSHIFT 75.0f

// ---------------- scratch (no allocations allowed) ----------------
__device__ float2 g_kv[2][NMAX];     // (k, v) packed per node
__device__ float  g_q[2][NMAX];
__device__ float2 g_qm[2][NMAX];     // (q, m2) packed per dst node
__device__ float2 g_sn[2][NMAX];     // (sum e, sum e*v*ms) per dst node
__device__ float  g_score[2][NMAX];
__device__ float  g_w[2][NMAX];
__device__ float  g_Mb[2][BMAX];
__device__ float  g_Sb[2][BMAX];
__device__ float  g_wsum[2];
__device__ float  g_kabs[2];         // global max |k| per graph

__device__ __forceinline__ void atomicMaxF(float* addr, float val) {
    if (val >= 0.0f) atomicMax((int*)addr, __float_as_int(val));
    else             atomicMin((unsigned int*)addr, __float_as_uint(val));
}

__device__ __forceinline__ void redAddF2(float2* addr, float a, float b) {
    unsigned long long p = (unsigned long long)__cvta_generic_to_global((void*)addr);
    asm volatile("red.global.add.v2.f32 [%0], {%1, %2};" :: "l"(p), "f"(a), "f"(b) : "memory");
}

// ---------------- init ----------------
__global__ void init_kernel() {
    int i = blockIdx.x * blockDim.x + threadIdx.x;
    int stride = gridDim.x * blockDim.x;
    float2 zero2 = make_float2(0.0f, 0.0f);
    for (int j = i; j < NMAX; j += stride) {
        g_sn[0][j] = zero2;  g_sn[1][j] = zero2;
    }
    if (i < BMAX) {
        g_Mb[0][i] = -INFINITY; g_Mb[1][i] = -INFINITY;
        g_Sb[0][i] = 0.0f;      g_Sb[1][i] = 0.0f;
    }
    if (i < 2) g_kabs[i] = 0.0f;
}

// ---------------- sum of w vectors ----------------
__global__ void wsum_kernel(const float* __restrict__ wa, const float* __restrict__ wb) {
    const float* w = blockIdx.x ? wb : wa;
    __shared__ float sh[8];
    float v = w[threadIdx.x];
    #pragma unroll
    for (int o = 16; o; o >>= 1) v += __shfl_xor_sync(0xffffffffu, v, o);
    if ((threadIdx.x & 31) == 0) sh[threadIdx.x >> 5] = v;
    __syncthreads();
    if (threadIdx.x == 0) {
        float t = 0.0f;
        #pragma unroll
        for (int j = 0; j < 8; j++) t += sh[j];
        g_wsum[blockIdx.x] = t;
    }
}

// ---------------- kqv: both graphs, 2 nodes per warp iteration; tracks max|k| ----------------
__global__ void kqv_kernel(const float* __restrict__ xi, const float* __restrict__ xn,
                           const float* __restrict__ Wi, const float* __restrict__ Wn,
                           const float* __restrict__ bI, const float* __restrict__ bN,
                           int Ni, int Nn) {
    int g = blockIdx.y;
    const float* __restrict__ x = g ? xn : xi;
    const float* __restrict__ W = g ? Wn : Wi;
    const float* __restrict__ bb = g ? bN : bI;
    int N = g ? Nn : Ni;

    int gtid = blockIdx.x * blockDim.x + threadIdx.x;
    int warp = gtid >> 5, lane = gtid & 31;
    int nwarps = (gridDim.x * blockDim.x) >> 5;

    float wk[8], wq[8], wv[8];
    #pragma unroll
    for (int i = 0; i < 2; i++) {
        #pragma unroll
        for (int c = 0; c < 4; c++) {
            int d = (lane + 32 * i) * 4 + c;
            wk[i * 4 + c] = W[d * 3 + 0];
            wq[i * 4 + c] = W[d * 3 + 1];
            wv[i * 4 + c] = W[d * 3 + 2];
        }
    }
    float b0 = bb[0], b1 = bb[1], b2 = bb[2];
    float kabs = 0.0f;

    for (int n = warp * 2; n < N; n += nwarps * 2) {
        bool two = (n + 1 < N);
        const float4* xa = (const float4*)(x + (size_t)n * DD);
        const float4* xb = (const float4*)(x + (size_t)(two ? n + 1 : n) * DD);
        float4 a0 = __ldg(&xa[lane]);
        float4 a1 = __ldg(&xa[lane + 32]);
        float4 c0 = __ldg(&xb[lane]);
        float4 c1 = __ldg(&xb[lane + 32]);

        float ka, qa, va, kc, qc, vc;
        ka = a0.x*wk[0] + a0.y*wk[1] + a0.z*wk[2] + a0.w*wk[3]
           + a1.x*wk[4] + a1.y*wk[5] + a1.z*wk[6] + a1.w*wk[7];
        qa = a0.x*wq[0] + a0.y*wq[1] + a0.z*wq[2] + a0.w*wq[3]
           + a1.x*wq[4] + a1.y*wq[5] + a1.z*wq[6] + a1.w*wq[7];
        va = a0.x*wv[0] + a0.y*wv[1] + a0.z*wv[2] + a0.w*wv[3]
           + a1.x*wv[4] + a1.y*wv[5] + a1.z*wv[6] + a1.w*wv[7];
        kc = c0.x*wk[0] + c0.y*wk[1] + c0.z*wk[2] + c0.w*wk[3]
           + c1.x*wk[4] + c1.y*wk[5] + c1.z*wk[6] + c1.w*wk[7];
        qc = c0.x*wq[0] + c0.y*wq[1] + c0.z*wq[2] + c0.w*wq[3]
           + c1.x*wq[4] + c1.y*wq[5] + c1.z*wq[6] + c1.w*wq[7];
        vc = c0.x*wv[0] + c0.y*wv[1] + c0.z*wv[2] + c0.w*wv[3]
           + c1.x*wv[4] + c1.y*wv[5] + c1.z*wv[6] + c1.w*wv[7];

        #pragma unroll
        for (int o = 16; o; o >>= 1) {
            ka += __shfl_xor_sync(0xffffffffu, ka, o);
            qa += __shfl_xor_sync(0xffffffffu, qa, o);
            va += __shfl_xor_sync(0xffffffffu, va, o);
            kc += __shfl_xor_sync(0xffffffffu, kc, o);
            qc += __shfl_xor_sync(0xffffffffu, qc, o);
            vc += __shfl_xor_sync(0xffffffffu, vc, o);
        }
        float kaf = ka + b0, kcf = kc + b0;
        kabs = fmaxf(kabs, fabsf(kaf));
        if (two) kabs = fmaxf(kabs, fabsf(kcf));
        if (lane == 0) {
            g_kv[g][n] = make_float2(kaf, va + b2);
            g_q[g][n]  = qa + b1;
            if (two) {
                g_kv[g][n + 1] = make_float2(kcf, vc + b2);
                g_q[g][n + 1]  = qc + b1;
            }
        }
    }

    // block-reduce max|k| -> one atomic per block
    __shared__ float sm[8];
    if (lane == 0) sm[(threadIdx.x >> 5)] = kabs;
    __syncthreads();
    if (threadIdx.x == 0) {
        float m = sm[0];
        #pragma unroll
        for (int j = 1; j < 8; j++) m = fmaxf(m, sm[j]);
        atomicMaxF(&g_kabs[g], m);
    }
}

// ---------------- node mid pass: safe softmax shift m2, pack (q, m2) ----------------
__global__ void node_mid_kernel(int Ni, int Nn,
                                const float* aii, const float* pii,
                                const float* ani, const float* pni,
                                const float* ain, const float* pin_) {
    int g = blockIdx.y;
    int N = g ? Nn : Ni;
    int n = blockIdx.x * blockDim.x + threadIdx.x;
    if (n >= N) return;
    float q = g_q[g][n];
    float m;
    if (g == 0) {
        float Ki = g_kabs[0], Kn = g_kabs[1];
        float sc_ii = aii[0] * pii[0];
        float sc_ni = ani[0] * pni[0];
        m = fmaxf(fabsf(q * sc_ii) * Ki, fabsf(q * sc_ni) * Kn) - MSHIFT;
    } else {
        float Ki = g_kabs[0];
        float sc_in = ain[0] * pin_[0];
        m = fabsf(q * sc_in) * Ki - MSHIFT;
    }
    g_qm[g][n] = make_float2(q, m);
}

// ---------------- edge pass: (sum e, sum e*v*ms) via one v2 reduction ----------------
__global__ void edge_sum_kernel(const int* __restrict__ ii, const int* __restrict__ ni,
                                const int* __restrict__ in_,
                                int Eii, int Eni, int Ein,
                                const float* aii, const float* pii, const float* mii,
                                const float* ani, const float* pni, const float* mni,
                                const float* ain, const float* pin_, const float* min_) {
    int y = blockIdx.y;
    const int* __restrict__ ei; int E; const float2* __restrict__ kv;
    const float2* __restrict__ qm; float2* SN; float sc, ms;
    if (y == 0)      { ei = ii;  E = Eii; kv = g_kv[0]; qm = g_qm[0]; SN = g_sn[0]; sc = aii[0]*pii[0]; ms = mii[0]; }
    else if (y == 1) { ei = ni;  E = Eni; kv = g_kv[1]; qm = g_qm[0]; SN = g_sn[0]; sc = ani[0]*pni[0]; ms = mni[0]; }
    else             { ei = in_; E = Ein; kv = g_kv[0]; qm = g_qm[1]; SN = g_sn[1]; sc = ain[0]*pin_[0]; ms = min_[0]; }

    bool vec4 = ((E & 3) == 0);
    int stride = gridDim.x * blockDim.x * 4;
    for (int e = (blockIdx.x * blockDim.x + threadIdx.x) * 4; e < E; e += stride) {
        if (e + 4 <= E) {
            int s0, s1, s2, s3, d0, d1, d2, d3;
            if (vec4) {
                int4 sv = *(const int4*)(ei + e);
                int4 dv = *(const int4*)(ei + E + e);
                s0 = sv.x; s1 = sv.y; s2 = sv.z; s3 = sv.w;
                d0 = dv.x; d1 = dv.y; d2 = dv.z; d3 = dv.w;
            } else {
                s0 = __ldg(ei + e);     s1 = __ldg(ei + e + 1);
                s2 = __ldg(ei + e + 2); s3 = __ldg(ei + e + 3);
                d0 = __ldg(ei + E + e);     d1 = __ldg(ei + E + e + 1);
                d2 = __ldg(ei + E + e + 2); d3 = __ldg(ei + E + e + 3);
            }
            float2 kv0 = kv[s0], kv1 = kv[s1], kv2 = kv[s2], kv3 = kv[s3];
            float2 qm0 = qm[d0], qm1 = qm[d1], qm2 = qm[d2], qm3 = qm[d3];
            float e0 = __expf(qm0.x * sc * kv0.x - qm0.y);
            float e1 = __expf(qm1.x * sc * kv1.x - qm1.y);
            float e2 = __expf(qm2.x * sc * kv2.x - qm2.y);
            float e3 = __expf(qm3.x * sc * kv3.x - qm3.y);
            redAddF2(&SN[d0], e0, e0 * kv0.y * ms);
            redAddF2(&SN[d1], e1, e1 * kv1.y * ms);
            redAddF2(&SN[d2], e2, e2 * kv2.y * ms);
            redAddF2(&SN[d3], e3, e3 * kv3.y * ms);
        } else {
            for (int t = e; t < E; t++) {
                int s = __ldg(ei + t), d = __ldg(ei + E + t);
                float2 kvv = kv[s]; float2 qmv = qm[d];
                float ex = __expf(qmv.x * sc * kvv.x - qmv.y);
                redAddF2(&SN[d], ex, ex * kvv.y * ms);
            }
        }
    }
}

// ---------------- per-node: agg -> gelu -> score -> batch max (warp-aggregated) ----------------
__global__ void node_fin_kernel(const float* owi, const float* obi,
                                const float* own, const float* obn,
                                const float* bvi, const float* bvn,
                                const int* __restrict__ bti, const int* __restrict__ btn,
                                int Ni, int Nn) {
    int g = blockIdx.y;
    int N = g ? Nn : Ni;
    const int* __restrict__ batch = g ? btn : bti;
    float ow = g ? own[0] : owi[0];
    float ob = g ? obn[0] : obi[0];
    float wsum = g_wsum[g];
    float boff = (float)DD * (g ? bvn[0] : bvi[0]);

    int n = blockIdx.x * blockDim.x + threadIdx.x;
    int nc = min(n, N - 1);
    int b = batch[nc];
    float sc = -INFINITY;
    if (n < N) {
        float2 sn = g_sn[g][n];
        float agg = sn.y / (sn.x + 1e-16f);
        float attn = 0.5f * agg * (1.0f + erff(agg * 0.70710678118654752f)) * ow + ob;
        sc = attn * wsum + boff;
        g_score[g][n] = sc;
    }
    int b0 = __shfl_sync(0xffffffffu, b, 0);
    bool uni = __all_sync(0xffffffffu, b == b0);
    if (uni) {
        float v = sc;
        #pragma unroll
        for (int o = 16; o; o >>= 1) v = fmaxf(v, __shfl_xor_sync(0xffffffffu, v, o));
        if ((threadIdx.x & 31) == 0) atomicMaxF(&g_Mb[g][b0], v);
    } else if (n < N) {
        atomicMaxF(&g_Mb[g][b], sc);
    }
}

// ---------------- per-node: w = exp(score - Mb), Sb (warp-aggregated) ----------------
__global__ void node_w_kernel(const int* __restrict__ bti, const int* __restrict__ btn,
                              int Ni, int Nn) {
    int g = blockIdx.y;
    int N = g ? Nn : Ni;
    const int* __restrict__ batch = g ? btn : bti;

    int n = blockIdx.x * blockDim.x + threadIdx.x;
    int nc = min(n, N - 1);
    int b = batch[nc];
    float w = 0.0f;
    if (n < N) {
        w = __expf(g_score[g][n] - g_Mb[g][b]);
        g_w[g][n] = w;
    }
    int b0 = __shfl_sync(0xffffffffu, b, 0);
    bool uni = __all_sync(0xffffffffu, b == b0);
    if (uni) {
        float v = w;
        #pragma unroll
        for (int o = 16; o; o >>= 1) v += __shfl_xor_sync(0xffffffffu, v, o);
        if ((threadIdx.x & 31) == 0) atomicAdd(&g_Sb[g][b0], v);
    } else if (n < N) {
        atomicAdd(&g_Sb[g][b], w);
    }
}

// ---------------- pooling: run-segmented weighted sum ----------------
__global__ void pool_kernel(const float* __restrict__ xi, const float* __restrict__ xn,
                            const int* __restrict__ bti, const int* __restrict__ btn,
                            int Ni, int Nn, float* __restrict__ out) {
    int g = blockIdx.y;
    const float* __restrict__ x = g ? xn : xi;
    const int* __restrict__ batch = g ? btn : bti;
    int N = g ? Nn : Ni;
    const float* __restrict__ w = g_w[g];
    float* outg = out + (size_t)g * BMAX * DD;

    int start = blockIdx.x * POOL_CHUNK;
    if (start >= N) return;
    int len = min(POOL_CHUNK, N - start);

    __shared__ float sw[POOL_CHUNK];
    __shared__ int sb[POOL_CHUNK];
    int t = threadIdx.x;
    if (t < len) { sw[t] = w[start + t]; sb[t] = batch[start + t]; }
    __syncthreads();

    const float* xrow = x + (size_t)start * DD + t;
    int i = 0;
    while (i < len) {
        int b = sb[i];
        int j = i + 1;
        while (j < len && sb[j] == b) ++j;
        float acc = 0.0f;
        int r = i;
        for (; r + 4 <= j; r += 4) {
            float x0 = xrow[(size_t)r * DD];
            float x1 = xrow[(size_t)(r + 1) * DD];
            float x2 = xrow[(size_t)(r + 2) * DD];
            float x3 = xrow[(size_t)(r + 3) * DD];
            acc += sw[r] * x0 + sw[r + 1] * x1 + sw[r + 2] * x2 + sw[r + 3] * x3;
        }
        for (; r < j; ++r) acc += sw[r] * xrow[(size_t)r * DD];
        atomicAdd(&outg[(size_t)b * DD + t], acc);
        i = j;
    }
}

// ---------------- final divide by Sb ----------------
__global__ void final_div_kernel(float* __restrict__ out) {
    int row = blockIdx.x;
    int graph = row >> 6, b = row & 63;
    out[(size_t)row * DD + threadIdx.x] /= (g_Sb[graph][b] + 1e-16f);
}

extern "C" void kernel_launch(void* const* d_in, const int* in_sizes, int n_in,
                              void* d_out, int out_size) {
    const float* x_i   = (const float*)d_in[0];
    const float* x_n   = (const float*)d_in[1];
    const int*   ei_ii = (const int*)d_in[2];
    const int*   ei_in = (const int*)d_in[3];
    const int*   ei_ni = (const int*)d_in[4];
    const int*   b_i   = (const int*)d_in[5];
    const int*   b_n   = (const int*)d_in[6];
    const float* Wi    = (const float*)d_in[7];
    const float* bi    = (const float*)d_in[8];
    const float* Wn    = (const float*)d_in[9];
    const float* bn    = (const float*)d_in[10];
    const float* a_ii  = (const float*)d_in[11];
    const float* m_ii  = (const float*)d_in[12];
    const float* p_ii  = (const float*)d_in[13];
    const float* a_in  = (const float*)d_in[14];
    const float* m_in  = (const float*)d_in[15];
    const float* p_in  = (const float*)d_in[16];
    const float* a_ni  = (const float*)d_in[17];
    const float* m_ni  = (const float*)d_in[18];
    const float* p_ni  = (const float*)d_in[19];
    const float* outw_i = (const float*)d_in[20];
    const float* outb_i = (const float*)d_in[21];
    const float* outw_n = (const float*)d_in[22];
    const float* outb_n = (const float*)d_in[23];
    const float* w_i    = (const float*)d_in[24];
    const float* bv_i   = (const float*)d_in[25];
    const float* w_n    = (const float*)d_in[26];
    const float* bv_n   = (const float*)d_in[27];

    int Ni  = in_sizes[0] / DD;
    int Nn  = in_sizes[1] / DD;
    int Eii = in_sizes[2] / 2;
    int Ein = in_sizes[3] / 2;
    int Eni = in_sizes[4] / 2;
    int Nmax = Ni > Nn ? Ni : Nn;

    float* out = (float*)d_out;

    cudaMemsetAsync(d_out, 0, (size_t)out_size * sizeof(float), 0);
    init_kernel<<<512, 256>>>();
    wsum_kernel<<<2, 256>>>(w_i, w_n);

    kqv_kernel<<<dim3(1024, 2), 256>>>(x_i, x_n, Wi, Wn, bi, bn, Ni, Nn);

    int nblk = (Nmax + 255) / 256;
    node_mid_kernel<<<dim3(nblk, 2), 256>>>(Ni, Nn, a_ii, p_ii, a_ni, p_ni, a_in, p_in);

    edge_sum_kernel<<<dim3(1536, 3), 256>>>(ei_ii, ei_ni, ei_in, Eii, Eni, Ein,
                                            a_ii, p_ii, m_ii, a_ni, p_ni, m_ni,
                                            a_in, p_in, m_in);

    node_fin_kernel<<<dim3(nblk, 2), 256>>>(outw_i, outb_i, outw_n, outb_n,
                                            bv_i, bv_n, b_i, b_n, Ni, Nn);
    node_w_kernel<<<dim3(nblk, 2), 256>>>(b_i, b_n, Ni, Nn);

    pool_kernel<<<dim3((Nmax + POOL_CHUNK - 1) / POOL_CHUNK, 2), 256>>>(
        x_i, x_n, b_i, b_n, Ni, Nn, out);

    final_div_kernel<<<2 * BMAX, 256>>>(out);
}

// round 5
// speedup vs baseline: 3.4059x; 1.0677x over previous
#include <cuda_runtime.h>
#include <math.h>

#define NMAX 200000
#define DD   256
#define BMAX 64
#define POOL_CHUNK 64
#define MSHIFT 75.0f

// ---------------- scratch (no allocations allowed) ----------------
__device__ float2 g_kv[2][NMAX];     // (k, v) packed per node
__device__ float  g_q[2][NMAX];
__device__ float2 g_qm[2][NMAX];     // (q, m2) packed per dst node
__device__ float2 g_sn[2][NMAX];     // (sum e, sum e*v*ms) per dst node
__device__ float  g_score[2][NMAX];
__device__ float  g_Mb[2][BMAX];
__device__ float  g_Sb[2][BMAX];
__device__ float  g_wsum[2];
__device__ float  g_kabs[2];         // global max |k| per graph

__device__ __forceinline__ void atomicMaxF(float* addr, float val) {
    if (val >= 0.0f) atomicMax((int*)addr, __float_as_int(val));
    else             atomicMin((unsigned int*)addr, __float_as_uint(val));
}

__device__ __forceinline__ void redAddF2(float2* addr, float a, float b) {
    unsigned long long p = (unsigned long long)__cvta_generic_to_global((void*)addr);
    asm volatile("red.global.add.v2.f32 [%0], {%1, %2};" :: "l"(p), "f"(a), "f"(b) : "memory");
}

// ---------------- init + wsum fused ----------------
__global__ void init_kernel(const float* __restrict__ wa, const float* __restrict__ wb) {
    int i = blockIdx.x * blockDim.x + threadIdx.x;
    int stride = gridDim.x * blockDim.x;
    float2 zero2 = make_float2(0.0f, 0.0f);
    for (int j = i; j < NMAX; j += stride) {
        g_sn[0][j] = zero2;  g_sn[1][j] = zero2;
    }
    if (i < BMAX) {
        g_Mb[0][i] = -INFINITY; g_Mb[1][i] = -INFINITY;
        g_Sb[0][i] = 0.0f;      g_Sb[1][i] = 0.0f;
    }
    if (i < 2) g_kabs[i] = 0.0f;

    if (blockIdx.x < 2) {   // blocks 0/1 also reduce the w vectors
        const float* w = blockIdx.x ? wb : wa;
        __shared__ float sh[8];
        float v = w[threadIdx.x];
        #pragma unroll
        for (int o = 16; o; o >>= 1) v += __shfl_xor_sync(0xffffffffu, v, o);
        if ((threadIdx.x & 31) == 0) sh[threadIdx.x >> 5] = v;
        __syncthreads();
        if (threadIdx.x == 0) {
            float t = 0.0f;
            #pragma unroll
            for (int j = 0; j < 8; j++) t += sh[j];
            g_wsum[blockIdx.x] = t;
        }
    }
}

// ---------------- kqv: 4 nodes per warp iteration, loads batched up front ----------------
__global__ void __launch_bounds__(256, 3)
kqv_kernel(const float* __restrict__ xi, const float* __restrict__ xn,
           const float* __restrict__ Wi, const float* __restrict__ Wn,
           const float* __restrict__ bI, const float* __restrict__ bN,
           int Ni, int Nn) {
    int g = blockIdx.y;
    const float* __restrict__ x = g ? xn : xi;
    const float* __restrict__ W = g ? Wn : Wi;
    const float* __restrict__ bb = g ? bN : bI;
    int N = g ? Nn : Ni;

    int gtid = blockIdx.x * blockDim.x + threadIdx.x;
    int warp = gtid >> 5, lane = gtid & 31;
    int nwarps = (gridDim.x * blockDim.x) >> 5;

    float wk[8], wq[8], wv[8];
    #pragma unroll
    for (int i = 0; i < 2; i++) {
        #pragma unroll
        for (int c = 0; c < 4; c++) {
            int d = (lane + 32 * i) * 4 + c;
            wk[i * 4 + c] = W[d * 3 + 0];
            wq[i * 4 + c] = W[d * 3 + 1];
            wv[i * 4 + c] = W[d * 3 + 2];
        }
    }
    float b0 = bb[0], b1 = bb[1], b2 = bb[2];
    float kabs = 0.0f;

    for (int n = warp * 4; n < N; n += nwarps * 4) {
        int nn[4];
        #pragma unroll
        for (int j = 0; j < 4; j++) nn[j] = min(n + j, N - 1);

        // batch all 8 loads before any compute
        float4 lo[4], hi[4];
        #pragma unroll
        for (int j = 0; j < 4; j++) {
            const float4* xr = (const float4*)(x + (size_t)nn[j] * DD);
            lo[j] = __ldg(&xr[lane]);
            hi[j] = __ldg(&xr[lane + 32]);
        }

        float pk[4], pq[4], pv[4];
        #pragma unroll
        for (int j = 0; j < 4; j++) {
            float4 a = lo[j], c = hi[j];
            pk[j] = a.x*wk[0] + a.y*wk[1] + a.z*wk[2] + a.w*wk[3]
                  + c.x*wk[4] + c.y*wk[5] + c.z*wk[6] + c.w*wk[7];
            pq[j] = a.x*wq[0] + a.y*wq[1] + a.z*wq[2] + a.w*wq[3]
                  + c.x*wq[4] + c.y*wq[5] + c.z*wq[6] + c.w*wq[7];
            pv[j] = a.x*wv[0] + a.y*wv[1] + a.z*wv[2] + a.w*wv[3]
                  + c.x*wv[4] + c.y*wv[5] + c.z*wv[6] + c.w*wv[7];
        }

        #pragma unroll
        for (int o = 16; o; o >>= 1) {
            #pragma unroll
            for (int j = 0; j < 4; j++) {
                pk[j] += __shfl_xor_sync(0xffffffffu, pk[j], o);
                pq[j] += __shfl_xor_sync(0xffffffffu, pq[j], o);
                pv[j] += __shfl_xor_sync(0xffffffffu, pv[j], o);
            }
        }
        #pragma unroll
        for (int j = 0; j < 4; j++) {
            float kf = pk[j] + b0;
            kabs = fmaxf(kabs, fabsf(kf));
            if (lane == 0) {
                g_kv[g][nn[j]] = make_float2(kf, pv[j] + b2);
                g_q[g][nn[j]]  = pq[j] + b1;
            }
        }
    }

    // block-reduce max|k| -> one atomic per block
    __shared__ float sm[8];
    if (lane == 0) sm[(threadIdx.x >> 5)] = kabs;
    __syncthreads();
    if (threadIdx.x == 0) {
        float m = sm[0];
        #pragma unroll
        for (int j = 1; j < 8; j++) m = fmaxf(m, sm[j]);
        atomicMaxF(&g_kabs[g], m);
    }
}

// ---------------- node mid pass: safe softmax shift m2, pack (q, m2) ----------------
__global__ void node_mid_kernel(int Ni, int Nn,
                                const float* aii, const float* pii,
                                const float* ani, const float* pni,
                                const float* ain, const float* pin_) {
    int g = blockIdx.y;
    int N = g ? Nn : Ni;
    int n = blockIdx.x * blockDim.x + threadIdx.x;
    if (n >= N) return;
    float q = g_q[g][n];
    float m;
    if (g == 0) {
        float Ki = g_kabs[0], Kn = g_kabs[1];
        float sc_ii = aii[0] * pii[0];
        float sc_ni = ani[0] * pni[0];
        m = fmaxf(fabsf(q * sc_ii) * Ki, fabsf(q * sc_ni) * Kn) - MSHIFT;
    } else {
        float Ki = g_kabs[0];
        float sc_in = ain[0] * pin_[0];
        m = fabsf(q * sc_in) * Ki - MSHIFT;
    }
    g_qm[g][n] = make_float2(q, m);
}

// ---------------- edge pass: (sum e, sum e*v*ms) via one v2 reduction ----------------
__global__ void edge_sum_kernel(const int* __restrict__ ii, const int* __restrict__ ni,
                                const int* __restrict__ in_,
                                int Eii, int Eni, int Ein,
                                const float* aii, const float* pii, const float* mii,
                                const float* ani, const float* pni, const float* mni,
                                const float* ain, const float* pin_, const float* min_) {
    int y = blockIdx.y;
    const int* __restrict__ ei; int E; const float2* __restrict__ kv;
    const float2* __restrict__ qm; float2* SN; float sc, ms;
    if (y == 0)      { ei = ii;  E = Eii; kv = g_kv[0]; qm = g_qm[0]; SN = g_sn[0]; sc = aii[0]*pii[0]; ms = mii[0]; }
    else if (y == 1) { ei = ni;  E = Eni; kv = g_kv[1]; qm = g_qm[0]; SN = g_sn[0]; sc = ani[0]*pni[0]; ms = mni[0]; }
    else             { ei = in_; E = Ein; kv = g_kv[0]; qm = g_qm[1]; SN = g_sn[1]; sc = ain[0]*pin_[0]; ms = min_[0]; }

    bool vec4 = ((E & 3) == 0);
    int stride = gridDim.x * blockDim.x * 4;
    for (int e = (blockIdx.x * blockDim.x + threadIdx.x) * 4; e < E; e += stride) {
        if (e + 4 <= E) {
            int s0, s1, s2, s3, d0, d1, d2, d3;
            if (vec4) {
                int4 sv = *(const int4*)(ei + e);
                int4 dv = *(const int4*)(ei + E + e);
                s0 = sv.x; s1 = sv.y; s2 = sv.z; s3 = sv.w;
                d0 = dv.x; d1 = dv.y; d2 = dv.z; d3 = dv.w;
            } else {
                s0 = __ldg(ei + e);     s1 = __ldg(ei + e + 1);
                s2 = __ldg(ei + e + 2); s3 = __ldg(ei + e + 3);
                d0 = __ldg(ei + E + e);     d1 = __ldg(ei + E + e + 1);
                d2 = __ldg(ei + E + e + 2); d3 = __ldg(ei + E + e + 3);
            }
            float2 kv0 = __ldg(&kv[s0]), kv1 = __ldg(&kv[s1]);
            float2 kv2 = __ldg(&kv[s2]), kv3 = __ldg(&kv[s3]);
            float2 qm0 = __ldg(&qm[d0]), qm1 = __ldg(&qm[d1]);
            float2 qm2 = __ldg(&qm[d2]), qm3 = __ldg(&qm[d3]);
            float e0 = __expf(qm0.x * sc * kv0.x - qm0.y);
            float e1 = __expf(qm1.x * sc * kv1.x - qm1.y);
            float e2 = __expf(qm2.x * sc * kv2.x - qm2.y);
            float e3 = __expf(qm3.x * sc * kv3.x - qm3.y);
            redAddF2(&SN[d0], e0, e0 * kv0.y * ms);
            redAddF2(&SN[d1], e1, e1 * kv1.y * ms);
            redAddF2(&SN[d2], e2, e2 * kv2.y * ms);
            redAddF2(&SN[d3], e3, e3 * kv3.y * ms);
        } else {
            for (int t = e; t < E; t++) {
                int s = __ldg(ei + t), d = __ldg(ei + E + t);
                float2 kvv = __ldg(&kv[s]); float2 qmv = __ldg(&qm[d]);
                float ex = __expf(qmv.x * sc * kvv.x - qmv.y);
                redAddF2(&SN[d], ex, ex * kvv.y * ms);
            }
        }
    }
}

// ---------------- per-node: agg -> gelu -> score -> batch max (warp-aggregated) ----------------
__global__ void node_fin_kernel(const float* owi, const float* obi,
                                const float* own, const float* obn,
                                const float* bvi, const float* bvn,
                                const int* __restrict__ bti, const int* __restrict__ btn,
                                int Ni, int Nn) {
    int g = blockIdx.y;
    int N = g ? Nn : Ni;
    const int* __restrict__ batch = g ? btn : bti;
    float ow = g ? own[0] : owi[0];
    float ob = g ? obn[0] : obi[0];
    float wsum = g_wsum[g];
    float boff = (float)DD * (g ? bvn[0] : bvi[0]);

    int n = blockIdx.x * blockDim.x + threadIdx.x;
    int nc = min(n, N - 1);
    int b = batch[nc];
    float sc = -INFINITY;
    if (n < N) {
        float2 sn = g_sn[g][n];
        float agg = sn.y / (sn.x + 1e-16f);
        float attn = 0.5f * agg * (1.0f + erff(agg * 0.70710678118654752f)) * ow + ob;
        sc = attn * wsum + boff;
        g_score[g][n] = sc;
    }
    int b0 = __shfl_sync(0xffffffffu, b, 0);
    bool uni = __all_sync(0xffffffffu, b == b0);
    if (uni) {
        float v = sc;
        #pragma unroll
        for (int o = 16; o; o >>= 1) v = fmaxf(v, __shfl_xor_sync(0xffffffffu, v, o));
        if ((threadIdx.x & 31) == 0) atomicMaxF(&g_Mb[g][b0], v);
    } else if (n < N) {
        atomicMaxF(&g_Mb[g][b], sc);
    }
}

// ---------------- pooling: inline w = exp(score - Mb); out += w*x; Sb += w ----------------
__global__ void pool_kernel(const float* __restrict__ xi, const float* __restrict__ xn,
                            const int* __restrict__ bti, const int* __restrict__ btn,
                            int Ni, int Nn, float* __restrict__ out) {
    int g = blockIdx.y;
    const float* __restrict__ x = g ? xn : xi;
    const int* __restrict__ batch = g ? btn : bti;
    int N = g ? Nn : Ni;
    float* outg = out + (size_t)g * BMAX * DD;

    int start = blockIdx.x * POOL_CHUNK;
    if (start >= N) return;
    int len = min(POOL_CHUNK, N - start);

    __shared__ float sMb[BMAX];
    __shared__ float sw[POOL_CHUNK];
    __shared__ int sb[POOL_CHUNK];
    int t = threadIdx.x;
    if (t < BMAX) sMb[t] = g_Mb[g][t];
    __syncthreads();
    if (t < len) {
        int b = batch[start + t];
        sb[t] = b;
        sw[t] = __expf(g_score[g][start + t] - sMb[b]);
    }
    __syncthreads();

    const float* xrow = x + (size_t)start * DD + t;
    int i = 0;
    while (i < len) {
        int b = sb[i];
        int j = i + 1;
        while (j < len && sb[j] == b) ++j;
        float acc = 0.0f;
        float wl = 0.0f;
        int r = i;
        for (; r + 8 <= j; r += 8) {
            float x0 = xrow[(size_t)r * DD];
            float x1 = xrow[(size_t)(r + 1) * DD];
            float x2 = xrow[(size_t)(r + 2) * DD];
            float x3 = xrow[(size_t)(r + 3) * DD];
            float x4 = xrow[(size_t)(r + 4) * DD];
            float x5 = xrow[(size_t)(r + 5) * DD];
            float x6 = xrow[(size_t)(r + 6) * DD];
            float x7 = xrow[(size_t)(r + 7) * DD];
            acc += sw[r]*x0 + sw[r+1]*x1 + sw[r+2]*x2 + sw[r+3]*x3
                 + sw[r+4]*x4 + sw[r+5]*x5 + sw[r+6]*x6 + sw[r+7]*x7;
            wl  += sw[r] + sw[r+1] + sw[r+2] + sw[r+3]
                 + sw[r+4] + sw[r+5] + sw[r+6] + sw[r+7];
        }
        for (; r < j; ++r) { acc += sw[r] * xrow[(size_t)r * DD]; wl += sw[r]; }
        atomicAdd(&outg[(size_t)b * DD + t], acc);
        if (t == 0) atomicAdd(&g_Sb[g][b], wl);
        i = j;
    }
}

// ---------------- final divide by Sb ----------------
__global__ void final_div_kernel(float* __restrict__ out) {
    int row = blockIdx.x;
    int graph = row >> 6, b = row & 63;
    out[(size_t)row * DD + threadIdx.x] /= (g_Sb[graph][b] + 1e-16f);
}

extern "C" void kernel_launch(void* const* d_in, const int* in_sizes, int n_in,
                              void* d_out, int out_size) {
    const float* x_i   = (const float*)d_in[0];
    const float* x_n   = (const float*)d_in[1];
    const int*   ei_ii = (const int*)d_in[2];
    const int*   ei_in = (const int*)d_in[3];
    const int*   ei_ni = (const int*)d_in[4];
    const int*   b_i   = (const int*)d_in[5];
    const int*   b_n   = (const int*)d_in[6];
    const float* Wi    = (const float*)d_in[7];
    const float* bi    = (const float*)d_in[8];
    const float* Wn    = (const float*)d_in[9];
    const float* bn    = (const float*)d_in[10];
    const float* a_ii  = (const float*)d_in[11];
    const float* m_ii  = (const float*)d_in[12];
    const float* p_ii  = (const float*)d_in[13];
    const float* a_in  = (const float*)d_in[14];
    const float* m_in  = (const float*)d_in[15];
    const float* p_in  = (const float*)d_in[16];
    const float* a_ni  = (const float*)d_in[17];
    const float* m_ni  = (const float*)d_in[18];
    const float* p_ni  = (const float*)d_in[19];
    const float* outw_i = (const float*)d_in[20];
    const float* outb_i = (const float*)d_in[21];
    const float* outw_n = (const float*)d_in[22];
    const float* outb_n = (const float*)d_in[23];
    const float* w_i    = (const float*)d_in[24];
    const float* bv_i   = (const float*)d_in[25];
    const float* w_n    = (const float*)d_in[26];
    const float* bv_n   = (const float*)d_in[27];

    int Ni  = in_sizes[0] / DD;
    int Nn  = in_sizes[1] / DD;
    int Eii = in_sizes[2] / 2;
    int Ein = in_sizes[3] / 2;
    int Eni = in_sizes[4] / 2;
    int Nmax = Ni > Nn ? Ni : Nn;

    float* out = (float*)d_out;

    cudaMemsetAsync(d_out, 0, (size_t)out_size * sizeof(float), 0);
    init_kernel<<<512, 256>>>(w_i, w_n);

    kqv_kernel<<<dim3(1024, 2), 256>>>(x_i, x_n, Wi, Wn, bi, bn, Ni, Nn);

    int nblk = (Nmax + 255) / 256;
    node_mid_kernel<<<dim3(nblk, 2), 256>>>(Ni, Nn, a_ii, p_ii, a_ni, p_ni, a_in, p_in);

    edge_sum_kernel<<<dim3(1536, 3), 256>>>(ei_ii, ei_ni, ei_in, Eii, Eni, Ein,
                                            a_ii, p_ii, m_ii, a_ni, p_ni, m_ni,
                                            a_in, p_in, m_in);

    node_fin_kernel<<<dim3(nblk, 2), 256>>>(outw_i, outb_i, outw_n, outb_n,
                                            bv_i, bv_n, b_i, b_n, Ni, Nn);

    pool_kernel<<<dim3((Nmax + POOL_CHUNK - 1) / POOL_CHUNK, 2), 256>>>(
        x_i, x_n, b_i, b_n, Ni, Nn, out);

    final_div_kernel<<<2 * BMAX, 256>>>(out);
}

// round 6
// speedup vs baseline: 3.4829x; 1.0226x over previous
#include <cuda_runtime.h>
#include <math.h>

#define NMAX 200000
#define DD   256
#define BMAX 64
#define POOL_CHUNK 64
#define MSHIFT 75.0f

// ---------------- scratch (no allocations allowed) ----------------
__device__ float2 g_kv[2][NMAX];     // (k, v) packed per node
__device__ float  g_q[2][NMAX];
__device__ float2 g_sn[2][NMAX];     // (sum e, sum e*v*ms) per dst node
__device__ float  g_score[2][NMAX];
__device__ float  g_Mb[2][BMAX];
__device__ float  g_Sb[2][BMAX];
__device__ float  g_wsum[2];
__device__ float  g_kabs[2];         // max-accumulator (>=0); stale value is idempotent

__device__ __forceinline__ void atomicMaxF(float* addr, float val) {
    if (val >= 0.0f) atomicMax((int*)addr, __float_as_int(val));
    else             atomicMin((unsigned int*)addr, __float_as_uint(val));
}

__device__ __forceinline__ void redAddF2(float2* addr, float a, float b) {
    unsigned long long p = (unsigned long long)__cvta_generic_to_global((void*)addr);
    asm volatile("red.global.add.v2.f32 [%0], {%1, %2};" :: "l"(p), "f"(a), "f"(b) : "memory");
}

// streaming int4 load that does not allocate in L1 (keeps L1 for gathers)
__device__ __forceinline__ int4 ldg_stream_int4(const int* p) {
    int4 v;
    asm("ld.global.nc.L1::no_allocate.v4.s32 {%0,%1,%2,%3}, [%4];"
        : "=r"(v.x), "=r"(v.y), "=r"(v.z), "=r"(v.w) : "l"(p));
    return v;
}

// ---------------- kqv: prologue does all per-run init; 4 nodes per warp iter ----------------
__global__ void __launch_bounds__(256, 3)
kqv_kernel(const float* __restrict__ xi, const float* __restrict__ xn,
           const float* __restrict__ Wi, const float* __restrict__ Wn,
           const float* __restrict__ bI, const float* __restrict__ bN,
           const float* __restrict__ wvi, const float* __restrict__ wvn,
           int Ni, int Nn) {
    int g = blockIdx.y;

    // ---- per-run init (idempotent; consumed only by later kernels) ----
    {
        int i = blockIdx.x * blockDim.x + threadIdx.x;
        int stride = gridDim.x * blockDim.x;
        float2 zero2 = make_float2(0.0f, 0.0f);
        for (int j = i; j < NMAX; j += stride) g_sn[g][j] = zero2;
        if (blockIdx.x == 0 && threadIdx.x < BMAX) {
            g_Mb[g][threadIdx.x] = -INFINITY;
            g_Sb[g][threadIdx.x] = 0.0f;
        }
        if (blockIdx.x == 0) {  // wsum reduction for this graph
            const float* w = g ? wvn : wvi;
            __shared__ float shw[8];
            float v = w[threadIdx.x];
            #pragma unroll
            for (int o = 16; o; o >>= 1) v += __shfl_xor_sync(0xffffffffu, v, o);
            if ((threadIdx.x & 31) == 0) shw[threadIdx.x >> 5] = v;
            __syncthreads();
            if (threadIdx.x == 0) {
                float t = 0.0f;
                #pragma unroll
                for (int j = 0; j < 8; j++) t += shw[j];
                g_wsum[g] = t;
            }
        }
    }

    const float* __restrict__ x = g ? xn : xi;
    const float* __restrict__ W = g ? Wn : Wi;
    const float* __restrict__ bb = g ? bN : bI;
    int N = g ? Nn : Ni;

    int gtid = blockIdx.x * blockDim.x + threadIdx.x;
    int warp = gtid >> 5, lane = gtid & 31;
    int nwarps = (gridDim.x * blockDim.x) >> 5;

    float wk[8], wq[8], wv[8];
    #pragma unroll
    for (int i = 0; i < 2; i++) {
        #pragma unroll
        for (int c = 0; c < 4; c++) {
            int d = (lane + 32 * i) * 4 + c;
            wk[i * 4 + c] = W[d * 3 + 0];
            wq[i * 4 + c] = W[d * 3 + 1];
            wv[i * 4 + c] = W[d * 3 + 2];
        }
    }
    float b0 = bb[0], b1 = bb[1], b2 = bb[2];
    float kabs = 0.0f;

    for (int n = warp * 4; n < N; n += nwarps * 4) {
        int nn[4];
        #pragma unroll
        for (int j = 0; j < 4; j++) nn[j] = min(n + j, N - 1);

        float4 lo[4], hi[4];
        #pragma unroll
        for (int j = 0; j < 4; j++) {
            const float4* xr = (const float4*)(x + (size_t)nn[j] * DD);
            lo[j] = __ldg(&xr[lane]);
            hi[j] = __ldg(&xr[lane + 32]);
        }

        float pk[4], pq[4], pv[4];
        #pragma unroll
        for (int j = 0; j < 4; j++) {
            float4 a = lo[j], c = hi[j];
            pk[j] = a.x*wk[0] + a.y*wk[1] + a.z*wk[2] + a.w*wk[3]
                  + c.x*wk[4] + c.y*wk[5] + c.z*wk[6] + c.w*wk[7];
            pq[j] = a.x*wq[0] + a.y*wq[1] + a.z*wq[2] + a.w*wq[3]
                  + c.x*wq[4] + c.y*wq[5] + c.z*wq[6] + c.w*wq[7];
            pv[j] = a.x*wv[0] + a.y*wv[1] + a.z*wv[2] + a.w*wv[3]
                  + c.x*wv[4] + c.y*wv[5] + c.z*wv[6] + c.w*wv[7];
        }

        #pragma unroll
        for (int o = 16; o; o >>= 1) {
            #pragma unroll
            for (int j = 0; j < 4; j++) {
                pk[j] += __shfl_xor_sync(0xffffffffu, pk[j], o);
                pq[j] += __shfl_xor_sync(0xffffffffu, pq[j], o);
                pv[j] += __shfl_xor_sync(0xffffffffu, pv[j], o);
            }
        }
        #pragma unroll
        for (int j = 0; j < 4; j++) {
            float kf = pk[j] + b0;
            kabs = fmaxf(kabs, fabsf(kf));
            if (lane == 0) {
                g_kv[g][nn[j]] = make_float2(kf, pv[j] + b2);
                g_q[g][nn[j]]  = pq[j] + b1;
            }
        }
    }

    __shared__ float sm[8];
    if (lane == 0) sm[(threadIdx.x >> 5)] = kabs;
    __syncthreads();
    if (threadIdx.x == 0) {
        float m = sm[0];
        #pragma unroll
        for (int j = 1; j < 8; j++) m = fmaxf(m, sm[j]);
        atomicMaxF(&g_kabs[g], m);   // >=0; bss-zero first run, stale==final on replay
    }
}

// ---------------- edge pass: e=exp(q*sc*k - (|q|C - 75)); red (S, N) ----------------
__global__ void edge_sum_kernel(const int* __restrict__ ii, const int* __restrict__ ni,
                                const int* __restrict__ in_,
                                int Eii, int Eni, int Ein,
                                const float* aii, const float* pii, const float* mii,
                                const float* ani, const float* pni, const float* mni,
                                const float* ain, const float* pin_, const float* min_) {
    int y = blockIdx.y;
    const int* __restrict__ ei; int E; const float2* __restrict__ kv;
    const float* __restrict__ q; float2* SN; float sc, ms, C;
    float Ki = g_kabs[0], Kn = g_kabs[1];
    float C0 = fmaxf(fabsf(aii[0] * pii[0]) * Ki, fabsf(ani[0] * pni[0]) * Kn);
    if (y == 0)      { ei = ii;  E = Eii; kv = g_kv[0]; q = g_q[0]; SN = g_sn[0]; sc = aii[0]*pii[0]; ms = mii[0]; C = C0; }
    else if (y == 1) { ei = ni;  E = Eni; kv = g_kv[1]; q = g_q[0]; SN = g_sn[0]; sc = ani[0]*pni[0]; ms = mni[0]; C = C0; }
    else             { ei = in_; E = Ein; kv = g_kv[0]; q = g_q[1]; SN = g_sn[1]; sc = ain[0]*pin_[0]; ms = min_[0]; C = fabsf(ain[0]*pin_[0]) * Ki; }

    bool vec4 = ((E & 3) == 0);
    int stride = gridDim.x * blockDim.x * 4;
    for (int e = (blockIdx.x * blockDim.x + threadIdx.x) * 4; e < E; e += stride) {
        if (e + 4 <= E) {
            int s0, s1, s2, s3, d0, d1, d2, d3;
            if (vec4) {
                int4 sv = ldg_stream_int4(ei + e);
                int4 dv = ldg_stream_int4(ei + E + e);
                s0 = sv.x; s1 = sv.y; s2 = sv.z; s3 = sv.w;
                d0 = dv.x; d1 = dv.y; d2 = dv.z; d3 = dv.w;
            } else {
                s0 = __ldg(ei + e);     s1 = __ldg(ei + e + 1);
                s2 = __ldg(ei + e + 2); s3 = __ldg(ei + e + 3);
                d0 = __ldg(ei + E + e);     d1 = __ldg(ei + E + e + 1);
                d2 = __ldg(ei + E + e + 2); d3 = __ldg(ei + E + e + 3);
            }
            float2 kv0 = __ldg(&kv[s0]), kv1 = __ldg(&kv[s1]);
            float2 kv2 = __ldg(&kv[s2]), kv3 = __ldg(&kv[s3]);
            float q0 = __ldg(&q[d0]), q1 = __ldg(&q[d1]);
            float q2 = __ldg(&q[d2]), q3 = __ldg(&q[d3]);
            float e0 = __expf(q0 * sc * kv0.x - (fabsf(q0) * C - MSHIFT));
            float e1 = __expf(q1 * sc * kv1.x - (fabsf(q1) * C - MSHIFT));
            float e2 = __expf(q2 * sc * kv2.x - (fabsf(q2) * C - MSHIFT));
            float e3 = __expf(q3 * sc * kv3.x - (fabsf(q3) * C - MSHIFT));
            redAddF2(&SN[d0], e0, e0 * kv0.y * ms);
            redAddF2(&SN[d1], e1, e1 * kv1.y * ms);
            redAddF2(&SN[d2], e2, e2 * kv2.y * ms);
            redAddF2(&SN[d3], e3, e3 * kv3.y * ms);
        } else {
            for (int t = e; t < E; t++) {
                int s = __ldg(ei + t), d = __ldg(ei + E + t);
                float2 kvv = __ldg(&kv[s]);
                float qv = __ldg(&q[d]);
                float ex = __expf(qv * sc * kvv.x - (fabsf(qv) * C - MSHIFT));
                redAddF2(&SN[d], ex, ex * kvv.y * ms);
            }
        }
    }
}

// ---------------- per-node: agg -> gelu -> score -> batch max (warp-aggregated) ----------------
__global__ void node_fin_kernel(const float* owi, const float* obi,
                                const float* own, const float* obn,
                                const float* bvi, const float* bvn,
                                const int* __restrict__ bti, const int* __restrict__ btn,
                                int Ni, int Nn) {
    int g = blockIdx.y;
    int N = g ? Nn : Ni;
    const int* __restrict__ batch = g ? btn : bti;
    float ow = g ? own[0] : owi[0];
    float ob = g ? obn[0] : obi[0];
    float wsum = g_wsum[g];
    float boff = (float)DD * (g ? bvn[0] : bvi[0]);

    int n = blockIdx.x * blockDim.x + threadIdx.x;
    int nc = min(n, N - 1);
    int b = batch[nc];
    float sc = -INFINITY;
    if (n < N) {
        float2 sn = g_sn[g][n];
        float agg = sn.y / (sn.x + 1e-16f);
        float attn = 0.5f * agg * (1.0f + erff(agg * 0.70710678118654752f)) * ow + ob;
        sc = attn * wsum + boff;
        g_score[g][n] = sc;
    }
    int b0 = __shfl_sync(0xffffffffu, b, 0);
    bool uni = __all_sync(0xffffffffu, b == b0);
    if (uni) {
        float v = sc;
        #pragma unroll
        for (int o = 16; o; o >>= 1) v = fmaxf(v, __shfl_xor_sync(0xffffffffu, v, o));
        if ((threadIdx.x & 31) == 0) atomicMaxF(&g_Mb[g][b0], v);
    } else if (n < N) {
        atomicMaxF(&g_Mb[g][b], sc);
    }
}

// ---------------- pooling: inline w = exp(score - Mb); out += w*x; Sb += w ----------------
__global__ void pool_kernel(const float* __restrict__ xi, const float* __restrict__ xn,
                            const int* __restrict__ bti, const int* __restrict__ btn,
                            int Ni, int Nn, float* __restrict__ out) {
    int g = blockIdx.y;
    const float* __restrict__ x = g ? xn : xi;
    const int* __restrict__ batch = g ? btn : bti;
    int N = g ? Nn : Ni;
    float* outg = out + (size_t)g * BMAX * DD;

    int start = blockIdx.x * POOL_CHUNK;
    if (start >= N) return;
    int len = min(POOL_CHUNK, N - start);

    __shared__ float sMb[BMAX];
    __shared__ float sw[POOL_CHUNK];
    __shared__ int sb[POOL_CHUNK];
    int t = threadIdx.x;
    if (t < BMAX) sMb[t] = g_Mb[g][t];
    __syncthreads();
    if (t < len) {
        int b = batch[start + t];
        sb[t] = b;
        sw[t] = __expf(g_score[g][start + t] - sMb[b]);
    }
    __syncthreads();

    const float* xrow = x + (size_t)start * DD + t;
    int i = 0;
    while (i < len) {
        int b = sb[i];
        int j = i + 1;
        while (j < len && sb[j] == b) ++j;
        float acc = 0.0f;
        float wl = 0.0f;
        int r = i;
        for (; r + 8 <= j; r += 8) {
            float x0 = xrow[(size_t)r * DD];
            float x1 = xrow[(size_t)(r + 1) * DD];
            float x2 = xrow[(size_t)(r + 2) * DD];
            float x3 = xrow[(size_t)(r + 3) * DD];
            float x4 = xrow[(size_t)(r + 4) * DD];
            float x5 = xrow[(size_t)(r + 5) * DD];
            float x6 = xrow[(size_t)(r + 6) * DD];
            float x7 = xrow[(size_t)(r + 7) * DD];
            acc += sw[r]*x0 + sw[r+1]*x1 + sw[r+2]*x2 + sw[r+3]*x3
                 + sw[r+4]*x4 + sw[r+5]*x5 + sw[r+6]*x6 + sw[r+7]*x7;
            wl  += sw[r] + sw[r+1] + sw[r+2] + sw[r+3]
                 + sw[r+4] + sw[r+5] + sw[r+6] + sw[r+7];
        }
        for (; r < j; ++r) { acc += sw[r] * xrow[(size_t)r * DD]; wl += sw[r]; }
        atomicAdd(&outg[(size_t)b * DD + t], acc);
        if (t == 0) atomicAdd(&g_Sb[g][b], wl);
        i = j;
    }
}

// ---------------- final divide by Sb ----------------
__global__ void final_div_kernel(float* __restrict__ out) {
    int row = blockIdx.x;
    int graph = row >> 6, b = row & 63;
    out[(size_t)row * DD + threadIdx.x] /= (g_Sb[graph][b] + 1e-16f);
}

extern "C" void kernel_launch(void* const* d_in, const int* in_sizes, int n_in,
                              void* d_out, int out_size) {
    const float* x_i   = (const float*)d_in[0];
    const float* x_n   = (const float*)d_in[1];
    const int*   ei_ii = (const int*)d_in[2];
    const int*   ei_in = (const int*)d_in[3];
    const int*   ei_ni = (const int*)d_in[4];
    const int*   b_i   = (const int*)d_in[5];
    const int*   b_n   = (const int*)d_in[6];
    const float* Wi    = (const float*)d_in[7];
    const float* bi    = (const float*)d_in[8];
    const float* Wn    = (const float*)d_in[9];
    const float* bn    = (const float*)d_in[10];
    const float* a_ii  = (const float*)d_in[11];
    const float* m_ii  = (const float*)d_in[12];
    const float* p_ii  = (const float*)d_in[13];
    const float* a_in  = (const float*)d_in[14];
    const float* m_in  = (const float*)d_in[15];
    const float* p_in  = (const float*)d_in[16];
    const float* a_ni  = (const float*)d_in[17];
    const float* m_ni  = (const float*)d_in[18];
    const float* p_ni  = (const float*)d_in[19];
    const float* outw_i = (const float*)d_in[20];
    const float* outb_i = (const float*)d_in[21];
    const float* outw_n = (const float*)d_in[22];
    const float* outb_n = (const float*)d_in[23];
    const float* w_i    = (const float*)d_in[24];
    const float* bv_i   = (const float*)d_in[25];
    const float* w_n    = (const float*)d_in[26];
    const float* bv_n   = (const float*)d_in[27];

    int Ni  = in_sizes[0] / DD;
    int Nn  = in_sizes[1] / DD;
    int Eii = in_sizes[2] / 2;
    int Ein = in_sizes[3] / 2;
    int Eni = in_sizes[4] / 2;
    int Nmax = Ni > Nn ? Ni : Nn;

    float* out = (float*)d_out;

    cudaMemsetAsync(d_out, 0, (size_t)out_size * sizeof(float), 0);

    kqv_kernel<<<dim3(1024, 2), 256>>>(x_i, x_n, Wi, Wn, bi, bn, w_i, w_n, Ni, Nn);

    edge_sum_kernel<<<dim3(1536, 3), 256>>>(ei_ii, ei_ni, ei_in, Eii, Eni, Ein,
                                            a_ii, p_ii, m_ii, a_ni, p_ni, m_ni,
                                            a_in, p_in, m_in);

    int nblk = (Nmax + 255) / 256;
    node_fin_kernel<<<dim3(nblk, 2), 256>>>(outw_i, outb_i, outw_n, outb_n,
                                            bv_i, bv_n, b_i, b_n, Ni, Nn);

    pool_kernel<<<dim3((Nmax + POOL_CHUNK - 1) / POOL_CHUNK, 2), 256>>>(
        x_i, x_n, b_i, b_n, Ni, Nn, out);

    final_div_kernel<<<2 * BMAX, 256>>>(out);
}

// round 7
// speedup vs baseline: 3.6194x; 1.0392x over previous
#include <cuda_runtime.h>
#include <math.h>

#define NMAX 200000
#define DD   256
#define BMAX 64
#define POOL_CHUNK 64
#define MSHIFT 75.0f

// ---------------- scratch (no allocations allowed) ----------------
__device__ float2 g_kv[2][NMAX];     // (k, v) packed per node
__device__ float  g_q[2][NMAX];
__device__ float2 g_sn[2][NMAX];     // (sum e, sum e*v*ms) per dst node
__device__ float  g_score[2][NMAX];
__device__ float  g_Mb[2][BMAX];
__device__ float  g_Sb[2][BMAX];
__device__ float  g_wsum[2];
__device__ float  g_kabs[2];         // max-accumulator (>=0); stale value is idempotent

__device__ __forceinline__ void atomicMaxF(float* addr, float val) {
    if (val >= 0.0f) atomicMax((int*)addr, __float_as_int(val));
    else             atomicMin((unsigned int*)addr, __float_as_uint(val));
}

__device__ __forceinline__ void redAddF2(float2* addr, float a, float b) {
    unsigned long long p = (unsigned long long)__cvta_generic_to_global((void*)addr);
    asm volatile("red.global.add.v2.f32 [%0], {%1, %2};" :: "l"(p), "f"(a), "f"(b) : "memory");
}

// streaming int4 load that does not allocate in L1 (keeps L1 for gathers)
__device__ __forceinline__ int4 ldg_stream_int4(const int* p) {
    int4 v;
    asm("ld.global.nc.L1::no_allocate.v4.s32 {%0,%1,%2,%3}, [%4];"
        : "=r"(v.x), "=r"(v.y), "=r"(v.z), "=r"(v.w) : "l"(p));
    return v;
}

// ---------------- kqv: prologue does all per-run init; 4 nodes per warp iter ----------------
__global__ void __launch_bounds__(256, 3)
kqv_kernel(const float* __restrict__ xi, const float* __restrict__ xn,
           const float* __restrict__ Wi, const float* __restrict__ Wn,
           const float* __restrict__ bI, const float* __restrict__ bN,
           const float* __restrict__ wvi, const float* __restrict__ wvn,
           int Ni, int Nn) {
    int g = blockIdx.y;

    // ---- per-run init (idempotent; consumed only by later kernels) ----
    {
        int i = blockIdx.x * blockDim.x + threadIdx.x;
        int stride = gridDim.x * blockDim.x;
        float2 zero2 = make_float2(0.0f, 0.0f);
        for (int j = i; j < NMAX; j += stride) g_sn[g][j] = zero2;
        if (blockIdx.x == 0 && threadIdx.x < BMAX) {
            g_Mb[g][threadIdx.x] = -INFINITY;
            g_Sb[g][threadIdx.x] = 0.0f;
        }
        if (blockIdx.x == 0) {  // wsum reduction for this graph
            const float* w = g ? wvn : wvi;
            __shared__ float shw[8];
            float v = w[threadIdx.x];
            #pragma unroll
            for (int o = 16; o; o >>= 1) v += __shfl_xor_sync(0xffffffffu, v, o);
            if ((threadIdx.x & 31) == 0) shw[threadIdx.x >> 5] = v;
            __syncthreads();
            if (threadIdx.x == 0) {
                float t = 0.0f;
                #pragma unroll
                for (int j = 0; j < 8; j++) t += shw[j];
                g_wsum[g] = t;
            }
        }
    }

    const float* __restrict__ x = g ? xn : xi;
    const float* __restrict__ W = g ? Wn : Wi;
    const float* __restrict__ bb = g ? bN : bI;
    int N = g ? Nn : Ni;

    int gtid = blockIdx.x * blockDim.x + threadIdx.x;
    int warp = gtid >> 5, lane = gtid & 31;
    int nwarps = (gridDim.x * blockDim.x) >> 5;

    float wk[8], wq[8], wv[8];
    #pragma unroll
    for (int i = 0; i < 2; i++) {
        #pragma unroll
        for (int c = 0; c < 4; c++) {
            int d = (lane + 32 * i) * 4 + c;
            wk[i * 4 + c] = W[d * 3 + 0];
            wq[i * 4 + c] = W[d * 3 + 1];
            wv[i * 4 + c] = W[d * 3 + 2];
        }
    }
    float b0 = bb[0], b1 = bb[1], b2 = bb[2];
    float kabs = 0.0f;

    for (int n = warp * 4; n < N; n += nwarps * 4) {
        int nn[4];
        #pragma unroll
        for (int j = 0; j < 4; j++) nn[j] = min(n + j, N - 1);

        float4 lo[4], hi[4];
        #pragma unroll
        for (int j = 0; j < 4; j++) {
            const float4* xr = (const float4*)(x + (size_t)nn[j] * DD);
            lo[j] = __ldg(&xr[lane]);
            hi[j] = __ldg(&xr[lane + 32]);
        }

        float pk[4], pq[4], pv[4];
        #pragma unroll
        for (int j = 0; j < 4; j++) {
            float4 a = lo[j], c = hi[j];
            pk[j] = a.x*wk[0] + a.y*wk[1] + a.z*wk[2] + a.w*wk[3]
                  + c.x*wk[4] + c.y*wk[5] + c.z*wk[6] + c.w*wk[7];
            pq[j] = a.x*wq[0] + a.y*wq[1] + a.z*wq[2] + a.w*wq[3]
                  + c.x*wq[4] + c.y*wq[5] + c.z*wq[6] + c.w*wq[7];
            pv[j] = a.x*wv[0] + a.y*wv[1] + a.z*wv[2] + a.w*wv[3]
                  + c.x*wv[4] + c.y*wv[5] + c.z*wv[6] + c.w*wv[7];
        }

        #pragma unroll
        for (int o = 16; o; o >>= 1) {
            #pragma unroll
            for (int j = 0; j < 4; j++) {
                pk[j] += __shfl_xor_sync(0xffffffffu, pk[j], o);
                pq[j] += __shfl_xor_sync(0xffffffffu, pq[j], o);
                pv[j] += __shfl_xor_sync(0xffffffffu, pv[j], o);
            }
        }
        #pragma unroll
        for (int j = 0; j < 4; j++) {
            float kf = pk[j] + b0;
            kabs = fmaxf(kabs, fabsf(kf));
            if (lane == 0) {
                g_kv[g][nn[j]] = make_float2(kf, pv[j] + b2);
                g_q[g][nn[j]]  = pq[j] + b1;
            }
        }
    }

    __shared__ float sm[8];
    if (lane == 0) sm[(threadIdx.x >> 5)] = kabs;
    __syncthreads();
    if (threadIdx.x == 0) {
        float m = sm[0];
        #pragma unroll
        for (int j = 1; j < 8; j++) m = fmaxf(m, sm[j]);
        atomicMaxF(&g_kabs[g], m);   // >=0; bss-zero first run, stale==final on replay
    }
}

// ---------------- edge pass: e=exp(q*sc*k - (|q|C - 75)); red (S, N) ----------------
__global__ void edge_sum_kernel(const int* __restrict__ ii, const int* __restrict__ ni,
                                const int* __restrict__ in_,
                                int Eii, int Eni, int Ein,
                                const float* aii, const float* pii, const float* mii,
                                const float* ani, const float* pni, const float* mni,
                                const float* ain, const float* pin_, const float* min_) {
    int y = blockIdx.y;
    const int* __restrict__ ei; int E; const float2* __restrict__ kv;
    const float* __restrict__ q; float2* SN; float sc, ms, C;
    float Ki = g_kabs[0], Kn = g_kabs[1];
    float C0 = fmaxf(fabsf(aii[0] * pii[0]) * Ki, fabsf(ani[0] * pni[0]) * Kn);
    if (y == 0)      { ei = ii;  E = Eii; kv = g_kv[0]; q = g_q[0]; SN = g_sn[0]; sc = aii[0]*pii[0]; ms = mii[0]; C = C0; }
    else if (y == 1) { ei = ni;  E = Eni; kv = g_kv[1]; q = g_q[0]; SN = g_sn[0]; sc = ani[0]*pni[0]; ms = mni[0]; C = C0; }
    else             { ei = in_; E = Ein; kv = g_kv[0]; q = g_q[1]; SN = g_sn[1]; sc = ain[0]*pin_[0]; ms = min_[0]; C = fabsf(ain[0]*pin_[0]) * Ki; }

    bool vec4 = ((E & 3) == 0);
    int stride = gridDim.x * blockDim.x * 4;
    for (int e = (blockIdx.x * blockDim.x + threadIdx.x) * 4; e < E; e += stride) {
        if (e + 4 <= E) {
            int s0, s1, s2, s3, d0, d1, d2, d3;
            if (vec4) {
                int4 sv = ldg_stream_int4(ei + e);
                int4 dv = ldg_stream_int4(ei + E + e);
                s0 = sv.x; s1 = sv.y; s2 = sv.z; s3 = sv.w;
                d0 = dv.x; d1 = dv.y; d2 = dv.z; d3 = dv.w;
            } else {
                s0 = __ldg(ei + e);     s1 = __ldg(ei + e + 1);
                s2 = __ldg(ei + e + 2); s3 = __ldg(ei + e + 3);
                d0 = __ldg(ei + E + e);     d1 = __ldg(ei + E + e + 1);
                d2 = __ldg(ei + E + e + 2); d3 = __ldg(ei + E + e + 3);
            }
            float2 kv0 = __ldg(&kv[s0]), kv1 = __ldg(&kv[s1]);
            float2 kv2 = __ldg(&kv[s2]), kv3 = __ldg(&kv[s3]);
            float q0 = __ldg(&q[d0]), q1 = __ldg(&q[d1]);
            float q2 = __ldg(&q[d2]), q3 = __ldg(&q[d3]);
            float e0 = __expf(q0 * sc * kv0.x - (fabsf(q0) * C - MSHIFT));
            float e1 = __expf(q1 * sc * kv1.x - (fabsf(q1) * C - MSHIFT));
            float e2 = __expf(q2 * sc * kv2.x - (fabsf(q2) * C - MSHIFT));
            float e3 = __expf(q3 * sc * kv3.x - (fabsf(q3) * C - MSHIFT));
            redAddF2(&SN[d0], e0, e0 * kv0.y * ms);
            redAddF2(&SN[d1], e1, e1 * kv1.y * ms);
            redAddF2(&SN[d2], e2, e2 * kv2.y * ms);
            redAddF2(&SN[d3], e3, e3 * kv3.y * ms);
        } else {
            for (int t = e; t < E; t++) {
                int s = __ldg(ei + t), d = __ldg(ei + E + t);
                float2 kvv = __ldg(&kv[s]);
                float qv = __ldg(&q[d]);
                float ex = __expf(qv * sc * kvv.x - (fabsf(qv) * C - MSHIFT));
                redAddF2(&SN[d], ex, ex * kvv.y * ms);
            }
        }
    }
}

// ---------------- per-node: agg -> gelu -> score -> batch max (warp-aggregated) ----------------
__global__ void node_fin_kernel(const float* owi, const float* obi,
                                const float* own, const float* obn,
                                const float* bvi, const float* bvn,
                                const int* __restrict__ bti, const int* __restrict__ btn,
                                int Ni, int Nn) {
    int g = blockIdx.y;
    int N = g ? Nn : Ni;
    const int* __restrict__ batch = g ? btn : bti;
    float ow = g ? own[0] : owi[0];
    float ob = g ? obn[0] : obi[0];
    float wsum = g_wsum[g];
    float boff = (float)DD * (g ? bvn[0] : bvi[0]);

    int n = blockIdx.x * blockDim.x + threadIdx.x;
    int nc = min(n, N - 1);
    int b = batch[nc];
    float sc = -INFINITY;
    if (n < N) {
        float2 sn = g_sn[g][n];
        float agg = sn.y / (sn.x + 1e-16f);
        float attn = 0.5f * agg * (1.0f + erff(agg * 0.70710678118654752f)) * ow + ob;
        sc = attn * wsum + boff;
        g_score[g][n] = sc;
    }
    int b0 = __shfl_sync(0xffffffffu, b, 0);
    bool uni = __all_sync(0xffffffffu, b == b0);
    if (uni) {
        float v = sc;
        #pragma unroll
        for (int o = 16; o; o >>= 1) v = fmaxf(v, __shfl_xor_sync(0xffffffffu, v, o));
        if ((threadIdx.x & 31) == 0) atomicMaxF(&g_Mb[g][b0], v);
    } else if (n < N) {
        atomicMaxF(&g_Mb[g][b], sc);
    }
}

// ---------------- pooling: 64 threads, one float4 feature slice per thread ----------------
__global__ void __launch_bounds__(64, 16)
pool_kernel(const float* __restrict__ xi, const float* __restrict__ xn,
            const int* __restrict__ bti, const int* __restrict__ btn,
            int Ni, int Nn, float* __restrict__ out) {
    int g = blockIdx.y;
    const float* __restrict__ x = g ? xn : xi;
    const int* __restrict__ batch = g ? btn : bti;
    int N = g ? Nn : Ni;
    float2* outg = (float2*)(out + (size_t)g * BMAX * DD);

    int start = blockIdx.x * POOL_CHUNK;
    if (start >= N) return;
    int len = min(POOL_CHUNK, N - start);

    __shared__ float sMb[BMAX];
    __shared__ float sw[POOL_CHUNK];
    __shared__ int sb[POOL_CHUNK];
    int t = threadIdx.x;                 // 0..63
    sMb[t] = g_Mb[g][t];
    __syncthreads();
    if (t < len) {
        int b = batch[start + t];
        sb[t] = b;
        sw[t] = __expf(g_score[g][start + t] - sMb[b]);
    }
    __syncthreads();

    // thread t owns features [4t, 4t+4); node r's slice is xrow[r*64]
    const float4* xrow = (const float4*)(x + (size_t)start * DD) + t;
    int i = 0;
    while (i < len) {
        int b = sb[i];
        int j = i + 1;
        while (j < len && sb[j] == b) ++j;
        float4 acc = make_float4(0.f, 0.f, 0.f, 0.f);
        float wl = 0.0f;
        int r = i;
        for (; r + 4 <= j; r += 4) {
            float4 x0 = xrow[(r + 0) * 64];
            float4 x1 = xrow[(r + 1) * 64];
            float4 x2 = xrow[(r + 2) * 64];
            float4 x3 = xrow[(r + 3) * 64];
            float w0 = sw[r], w1 = sw[r + 1], w2 = sw[r + 2], w3 = sw[r + 3];
            acc.x += w0*x0.x + w1*x1.x + w2*x2.x + w3*x3.x;
            acc.y += w0*x0.y + w1*x1.y + w2*x2.y + w3*x3.y;
            acc.z += w0*x0.z + w1*x1.z + w2*x2.z + w3*x3.z;
            acc.w += w0*x0.w + w1*x1.w + w2*x2.w + w3*x3.w;
            wl += w0 + w1 + w2 + w3;
        }
        for (; r < j; ++r) {
            float4 xv = xrow[r * 64];
            float w0 = sw[r];
            acc.x += w0*xv.x; acc.y += w0*xv.y; acc.z += w0*xv.z; acc.w += w0*xv.w;
            wl += w0;
        }
        redAddF2(&outg[b * (DD/2) + t*2],     acc.x, acc.y);
        redAddF2(&outg[b * (DD/2) + t*2 + 1], acc.z, acc.w);
        if (t == 0) atomicAdd(&g_Sb[g][b], wl);
        i = j;
    }
}

// ---------------- final divide by Sb ----------------
__global__ void final_div_kernel(float* __restrict__ out) {
    int row = blockIdx.x;
    int graph = row >> 6, b = row & 63;
    out[(size_t)row * DD + threadIdx.x] /= (g_Sb[graph][b] + 1e-16f);
}

extern "C" void kernel_launch(void* const* d_in, const int* in_sizes, int n_in,
                              void* d_out, int out_size) {
    const float* x_i   = (const float*)d_in[0];
    const float* x_n   = (const float*)d_in[1];
    const int*   ei_ii = (const int*)d_in[2];
    const int*   ei_in = (const int*)d_in[3];
    const int*   ei_ni = (const int*)d_in[4];
    const int*   b_i   = (const int*)d_in[5];
    const int*   b_n   = (const int*)d_in[6];
    const float* Wi    = (const float*)d_in[7];
    const float* bi    = (const float*)d_in[8];
    const float* Wn    = (const float*)d_in[9];
    const float* bn    = (const float*)d_in[10];
    const float* a_ii  = (const float*)d_in[11];
    const float* m_ii  = (const float*)d_in[12];
    const float* p_ii  = (const float*)d_in[13];
    const float* a_in  = (const float*)d_in[14];
    const float* m_in  = (const float*)d_in[15];
    const float* p_in  = (const float*)d_in[16];
    const float* a_ni  = (const float*)d_in[17];
    const float* m_ni  = (const float*)d_in[18];
    const float* p_ni  = (const float*)d_in[19];
    const float* outw_i = (const float*)d_in[20];
    const float* outb_i = (const float*)d_in[21];
    const float* outw_n = (const float*)d_in[22];
    const float* outb_n = (const float*)d_in[23];
    const float* w_i    = (const float*)d_in[24];
    const float* bv_i   = (const float*)d_in[25];
    const float* w_n    = (const float*)d_in[26];
    const float* bv_n   = (const float*)d_in[27];

    int Ni  = in_sizes[0] / DD;
    int Nn  = in_sizes[1] / DD;
    int Eii = in_sizes[2] / 2;
    int Ein = in_sizes[3] / 2;
    int Eni = in_sizes[4] / 2;
    int Nmax = Ni > Nn ? Ni : Nn;

    float* out = (float*)d_out;

    cudaMemsetAsync(d_out, 0, (size_t)out_size * sizeof(float), 0);

    kqv_kernel<<<dim3(1024, 2), 256>>>(x_i, x_n, Wi, Wn, bi, bn, w_i, w_n, Ni, Nn);

    edge_sum_kernel<<<dim3(1536, 3), 256>>>(ei_ii, ei_ni, ei_in, Eii, Eni, Ein,
                                            a_ii, p_ii, m_ii, a_ni, p_ni, m_ni,
                                            a_in, p_in, m_in);

    int nblk = (Nmax + 255) / 256;
    node_fin_kernel<<<dim3(nblk, 2), 256>>>(outw_i, outb_i, outw_n, outb_n,
                                            bv_i, bv_n, b_i, b_n, Ni, Nn);

    pool_kernel<<<dim3((Nmax + POOL_CHUNK - 1) / POOL_CHUNK, 2), 64>>>(
        x_i, x_n, b_i, b_n, Ni, Nn, out);

    final_div_kernel<<<2 * BMAX, 256>>>(out);
}